// round 1
// baseline (speedup 1.0000x reference)
#include <cuda_runtime.h>
#include <math.h>

#define D_MODEL 2048
#define D_FF    8192
#define BATCH   4
#define SEQ     2048
#define NTOK    (BATCH * SEQ)   // 8192 tokens

// ---------------------------------------------------------------------------
// Scratch (device globals; no allocation allowed)
// ---------------------------------------------------------------------------
__device__ float g_xln [(size_t)NTOK * D_MODEL];        //  64 MB  LN1 output (residual base!)
__device__ float g_qkv [(size_t)NTOK * 3 * D_MODEL];    // 192 MB
__device__ float g_q   [(size_t)NTOK * D_MODEL];        //  64 MB  RoPE'd Q
__device__ float g_k   [(size_t)NTOK * D_MODEL];        //  64 MB  RoPE'd K
__device__ float g_sc  [(size_t)BATCH * SEQ * SEQ];     //  64 MB  scores / probs
__device__ float g_attn[(size_t)NTOK * D_MODEL];        //  64 MB
__device__ float g_src2[(size_t)NTOK * D_MODEL];        //  64 MB  post-attn residual
__device__ float g_hln [(size_t)NTOK * D_MODEL];        //  64 MB  LN2 output
__device__ float g_h1  [(size_t)NTOK * D_FF];           // 256 MB  FFN hidden

// ---------------------------------------------------------------------------
// SGEMM: C = scale*(A @ op(B)) [+ bias] [+ residual] [relu]
//   BT=true : B is [N,K] row-major (compute A·B^T)   — all weight GEMMs, QK^T
//   BT=false: B is [K,N] row-major (compute A·B)     — P·V
// Block 128x128, K-tile 16, 256 threads, 8x8 per thread (split 4+4).
// All M,N multiples of 128; K multiple of 16 in this problem.
// ---------------------------------------------------------------------------
template <bool BT>
__global__ __launch_bounds__(256)
void sgemm_k(const float* __restrict__ A, int lda, long long sA,
             const float* __restrict__ B, int ldb, long long sB,
             float*       __restrict__ C, int ldc, long long sC,
             int K,
             const float* __restrict__ bias,
             const float* __restrict__ res,
             float scale, int relu)
{
    __shared__ float As[16][128];
    __shared__ float Bs[16][128];

    const long long bz = blockIdx.z;
    A += bz * sA;  B += bz * sB;  C += bz * sC;
    const float* R = res ? res + bz * sC : nullptr;

    const int bm = blockIdx.y * 128;
    const int bn = blockIdx.x * 128;
    const int tid = threadIdx.x;
    const int tx  = tid & 15;          // 0..15 -> N
    const int ty  = tid >> 4;          // 0..15 -> M
    const int ar  = tid >> 2;          // 0..63 (row within tile for K-major loads)
    const int ac  = (tid & 3) << 2;    // 0,4,8,12
    const int br8 = tid >> 5;          // 0..7  (NN B load row)
    const int bc  = (tid & 31) << 2;   // 0..124

    float acc[8][8];
#pragma unroll
    for (int i = 0; i < 8; i++)
#pragma unroll
        for (int j = 0; j < 8; j++) acc[i][j] = 0.f;

    for (int k0 = 0; k0 < K; k0 += 16) {
        // --- A tile: [128 rows x 16 k], transpose into As[k][m]
        float4 a0 = *(const float4*)(A + (long long)(bm + ar)      * lda + k0 + ac);
        float4 a1 = *(const float4*)(A + (long long)(bm + ar + 64) * lda + k0 + ac);
        As[ac + 0][ar] = a0.x; As[ac + 1][ar] = a0.y; As[ac + 2][ar] = a0.z; As[ac + 3][ar] = a0.w;
        As[ac + 0][ar + 64] = a1.x; As[ac + 1][ar + 64] = a1.y; As[ac + 2][ar + 64] = a1.z; As[ac + 3][ar + 64] = a1.w;

        if (BT) {
            float4 b0 = *(const float4*)(B + (long long)(bn + ar)      * ldb + k0 + ac);
            float4 b1 = *(const float4*)(B + (long long)(bn + ar + 64) * ldb + k0 + ac);
            Bs[ac + 0][ar] = b0.x; Bs[ac + 1][ar] = b0.y; Bs[ac + 2][ar] = b0.z; Bs[ac + 3][ar] = b0.w;
            Bs[ac + 0][ar + 64] = b1.x; Bs[ac + 1][ar + 64] = b1.y; Bs[ac + 2][ar + 64] = b1.z; Bs[ac + 3][ar + 64] = b1.w;
        } else {
            float4 b0 = *(const float4*)(B + (long long)(k0 + br8)     * ldb + bn + bc);
            float4 b1 = *(const float4*)(B + (long long)(k0 + br8 + 8) * ldb + bn + bc);
            *(float4*)&Bs[br8][bc]     = b0;
            *(float4*)&Bs[br8 + 8][bc] = b1;
        }
        __syncthreads();

#pragma unroll
        for (int kk = 0; kk < 16; kk++) {
            float4 va0 = *(const float4*)&As[kk][ty * 4];
            float4 va1 = *(const float4*)&As[kk][ty * 4 + 64];
            float4 vb0 = *(const float4*)&Bs[kk][tx * 4];
            float4 vb1 = *(const float4*)&Bs[kk][tx * 4 + 64];
            float av[8] = {va0.x, va0.y, va0.z, va0.w, va1.x, va1.y, va1.z, va1.w};
            float bv[8] = {vb0.x, vb0.y, vb0.z, vb0.w, vb1.x, vb1.y, vb1.z, vb1.w};
#pragma unroll
            for (int i = 0; i < 8; i++)
#pragma unroll
                for (int j = 0; j < 8; j++)
                    acc[i][j] += av[i] * bv[j];
        }
        __syncthreads();
    }

#pragma unroll
    for (int i = 0; i < 8; i++) {
        const int m = bm + ty * 4 + (i & 3) + ((i >> 2) << 6);
#pragma unroll
        for (int j = 0; j < 8; j++) {
            const int n = bn + tx * 4 + (j & 3) + ((j >> 2) << 6);
            float v = acc[i][j] * scale;
            if (bias) v += __ldg(bias + n);
            if (R)    v += R[(long long)m * ldc + n];
            if (relu) v = fmaxf(v, 0.f);
            C[(long long)m * ldc + n] = v;
        }
    }
}

// ---------------------------------------------------------------------------
// LayerNorm: one block per row, D = 2048, 256 threads x 8 elems
// ---------------------------------------------------------------------------
__global__ __launch_bounds__(256)
void ln_k(const float* __restrict__ x, const float* __restrict__ g,
          const float* __restrict__ b, float* __restrict__ y)
{
    const int D = D_MODEL;
    const long long row = blockIdx.x;
    const float* xr = x + row * D;
    float*       yr = y + row * D;
    const int tid = threadIdx.x;

    __shared__ float sh[256];
    float v[8];
    float s = 0.f;
#pragma unroll
    for (int i = 0; i < 8; i++) { v[i] = xr[tid + i * 256]; s += v[i]; }
    sh[tid] = s; __syncthreads();
    for (int o = 128; o > 0; o >>= 1) { if (tid < o) sh[tid] += sh[tid + o]; __syncthreads(); }
    const float mean = sh[0] * (1.f / D);
    __syncthreads();

    s = 0.f;
#pragma unroll
    for (int i = 0; i < 8; i++) { float d = v[i] - mean; s += d * d; }
    sh[tid] = s; __syncthreads();
    for (int o = 128; o > 0; o >>= 1) { if (tid < o) sh[tid] += sh[tid + o]; __syncthreads(); }
    const float r = rsqrtf(sh[0] * (1.f / D) + 1e-5f);

#pragma unroll
    for (int i = 0; i < 8; i++) {
        int j = tid + i * 256;
        yr[j] = (v[i] - mean) * r * __ldg(g + j) + __ldg(b + j);
    }
}

// ---------------------------------------------------------------------------
// RoPE (reference-exact, including cos(emb)/sin(emb) of the sinusoidal table)
//   emb[t,j] = sin(t*invf[j])            j < 1024
//            = cos(t*invf[j-1024])       j >= 1024
//   c = cos(emb), s = sin(emb)
//   rot(x)[j] = -x[2j] (j<1024) ; x[2(j-1024)+1] (j>=1024)
//   Q' = Q*c + rot(Q)*s ;  K' = K*c - rot(K)*s
// ---------------------------------------------------------------------------
__global__ __launch_bounds__(256)
void rope_k(const float* __restrict__ qkv, float* __restrict__ Qo, float* __restrict__ Ko)
{
    const int d = D_MODEL, half = D_MODEL / 2;
    const int t = blockIdx.x, b = blockIdx.y;
    const long long rq = ((long long)b * SEQ + t) * (3 * D_MODEL);
    const float* Q = qkv + rq;
    const float* K = qkv + rq + d;
    const long long ro = ((long long)b * SEQ + t) * d;
    const float pos = (float)t;

#pragma unroll
    for (int i = 0; i < 8; i++) {
        int j = threadIdx.x + i * 256;
        int fidx = (j < half) ? j : (j - half);
        float invf = powf(10000.0f, -(float)(2 * fidx) / (float)d);
        float sp = pos * invf;
        float e = (j < half) ? sinf(sp) : cosf(sp);
        float c = cosf(e), s = sinf(e);
        float rqv, rkv;
        if (j < half) { rqv = -Q[2 * j];            rkv = -K[2 * j]; }
        else          { rqv =  Q[2 * (j - half) + 1]; rkv =  K[2 * (j - half) + 1]; }
        Qo[ro + j] = Q[j] * c + rqv * s;
        Ko[ro + j] = K[j] * c - rkv * s;
    }
}

// ---------------------------------------------------------------------------
// Causal softmax in-place on scores rows (scale already applied in GEMM)
// ---------------------------------------------------------------------------
__global__ __launch_bounds__(256)
void softmax_k(float* __restrict__ P)
{
    const int S = SEQ;
    const int q = blockIdx.x, b = blockIdx.y;
    float* row = P + ((long long)b * S + q) * S;
    const int n = q + 1;                 // valid length
    const int tid = threadIdx.x;
    __shared__ float sh[256];

    float v[8];
    float mx = -3.402823e38f;
#pragma unroll
    for (int i = 0; i < 8; i++) {
        int j = tid + i * 256;
        v[i] = (j < n) ? row[j] : -3.402823e38f;
        mx = fmaxf(mx, v[i]);
    }
    sh[tid] = mx; __syncthreads();
    for (int o = 128; o > 0; o >>= 1) { if (tid < o) sh[tid] = fmaxf(sh[tid], sh[tid + o]); __syncthreads(); }
    mx = sh[0]; __syncthreads();

    float sum = 0.f;
#pragma unroll
    for (int i = 0; i < 8; i++) {
        int j = tid + i * 256;
        v[i] = (j < n) ? expf(v[i] - mx) : 0.f;
        sum += v[i];
    }
    sh[tid] = sum; __syncthreads();
    for (int o = 128; o > 0; o >>= 1) { if (tid < o) sh[tid] += sh[tid + o]; __syncthreads(); }
    const float inv = 1.f / sh[0];

#pragma unroll
    for (int i = 0; i < 8; i++) {
        int j = tid + i * 256;
        row[j] = v[i] * inv;
    }
}

// ---------------------------------------------------------------------------
// Launch
// ---------------------------------------------------------------------------
extern "C" void kernel_launch(void* const* d_in, const int* in_sizes, int n_in,
                              void* d_out, int out_size)
{
    const float* src  = (const float*)d_in[0];
    const float* Wqkv = (const float*)d_in[1];
    const float* bqkv = (const float*)d_in[2];
    const float* Wo   = (const float*)d_in[3];
    const float* bo   = (const float*)d_in[4];
    const float* W1   = (const float*)d_in[5];
    const float* b1   = (const float*)d_in[6];
    const float* W2   = (const float*)d_in[7];
    const float* b2   = (const float*)d_in[8];
    const float* g1   = (const float*)d_in[9];
    const float* be1  = (const float*)d_in[10];
    const float* g2   = (const float*)d_in[11];
    const float* be2  = (const float*)d_in[12];
    float* out = (float*)d_out;

    float *xln, *qkv, *q, *k, *sc, *attn, *src2, *hln, *h1;
    cudaGetSymbolAddress((void**)&xln,  g_xln);
    cudaGetSymbolAddress((void**)&qkv,  g_qkv);
    cudaGetSymbolAddress((void**)&q,    g_q);
    cudaGetSymbolAddress((void**)&k,    g_k);
    cudaGetSymbolAddress((void**)&sc,   g_sc);
    cudaGetSymbolAddress((void**)&attn, g_attn);
    cudaGetSymbolAddress((void**)&src2, g_src2);
    cudaGetSymbolAddress((void**)&hln,  g_hln);
    cudaGetSymbolAddress((void**)&h1,   g_h1);

    const int d = D_MODEL, f = D_FF, S = SEQ, B = BATCH, M = NTOK;
    const long long Sd  = (long long)S * d;
    const long long SS  = (long long)S * S;
    const long long S3d = (long long)S * 3 * d;
    const float attn_scale = 1.0f / sqrtf((float)d);

    // 1. LN1 (result is ALSO the residual base for attention)
    ln_k<<<M, 256>>>(src, g1, be1, xln);
    // 2. QKV projection: [8192,2048] x [6144,2048]^T
    sgemm_k<true><<<dim3(3 * d / 128, M / 128, 1), 256>>>(
        xln, d, 0, Wqkv, d, 0, qkv, 3 * d, 0, d, bqkv, nullptr, 1.f, 0);
    // 3. RoPE on Q,K
    rope_k<<<dim3(S, B), 256>>>(qkv, q, k);
    // 4. scores = scale * Q K^T  (batched)
    sgemm_k<true><<<dim3(S / 128, S / 128, B), 256>>>(
        q, d, Sd, k, d, Sd, sc, S, SS, d, nullptr, nullptr, attn_scale, 0);
    // 5. causal softmax
    softmax_k<<<dim3(S, B), 256>>>(sc);
    // 6. attn = P V   (NN; V lives inside qkv at column offset 2d, ld 3d)
    sgemm_k<false><<<dim3(d / 128, S / 128, B), 256>>>(
        sc, S, SS, qkv + 2 * d, 3 * d, S3d, attn, d, Sd, S, nullptr, nullptr, 1.f, 0);
    // 7. src2 = xln + attn Wo^T + bo
    sgemm_k<true><<<dim3(d / 128, M / 128, 1), 256>>>(
        attn, d, 0, Wo, d, 0, src2, d, 0, d, bo, xln, 1.f, 0);
    // 8. LN2
    ln_k<<<M, 256>>>(src2, g2, be2, hln);
    // 9. h1 = relu(hln W1^T + b1)
    sgemm_k<true><<<dim3(f / 128, M / 128, 1), 256>>>(
        hln, d, 0, W1, d, 0, h1, f, 0, d, b1, nullptr, 1.f, 1);
    // 10. out = src2 + h1 W2^T + b2
    sgemm_k<true><<<dim3(d / 128, M / 128, 1), 256>>>(
        h1, f, 0, W2, f, 0, out, d, 0, f, b2, src2, 1.f, 0);
}

// round 3
// speedup vs baseline: 3.0407x; 3.0407x over previous
#include <cuda_runtime.h>
#include <math.h>
#include <stdint.h>

#define D_MODEL 2048
#define D_FF    8192
#define BATCH   4
#define SEQ     2048
#define NTOK    (BATCH * SEQ)

// ---------------------------------------------------------------------------
// Scratch
// ---------------------------------------------------------------------------
__device__ float g_xln [(size_t)NTOK * D_MODEL];
__device__ float g_qkv [(size_t)NTOK * 3 * D_MODEL];
__device__ float g_q   [(size_t)NTOK * D_MODEL];
__device__ float g_k   [(size_t)NTOK * D_MODEL];
__device__ float g_vt  [(size_t)NTOK * D_MODEL];      // V^T  [B, d, S]
__device__ float g_sc  [(size_t)BATCH * SEQ * SEQ];
__device__ float g_attn[(size_t)NTOK * D_MODEL];
__device__ float g_src2[(size_t)NTOK * D_MODEL];
__device__ float g_hln [(size_t)NTOK * D_MODEL];
__device__ float g_h1  [(size_t)NTOK * D_FF];

__device__ __forceinline__ uint32_t f2tf32(float f) {
    uint32_t u; asm("cvt.rna.tf32.f32 %0, %1;" : "=r"(u) : "f"(f)); return u;
}

#define MMA_TF32(d, a, b)                                                      \
    asm volatile("mma.sync.aligned.m16n8k8.row.col.f32.tf32.tf32.f32 "         \
        "{%0,%1,%2,%3}, {%4,%5,%6,%7}, {%8,%9}, {%0,%1,%2,%3};"                \
        : "+f"((d)[0]), "+f"((d)[1]), "+f"((d)[2]), "+f"((d)[3])               \
        : "r"((a)[0]), "r"((a)[1]), "r"((a)[2]), "r"((a)[3]),                  \
          "r"((b)[0]), "r"((b)[1]))

// ---------------------------------------------------------------------------
// tf32 mma.sync GEMM: C[M,N] = scale*(A @ B^T) [+bias][+res][relu]
// A:[M,K] fp32 row-major, B:[N,K] fp32 row-major. M,N mult of 128, K of 32.
// CTA 128x128x32, 8 warps (2m x 4n), warp 64x32, frags m16n8k8.
// SMEM rows padded to 36 words -> conflict-free frag LDS.
// ---------------------------------------------------------------------------
#define PAD       36
#define TILE_W    (128 * PAD)            // words per (A or B) tile
#define STAGE_W   (2 * TILE_W)           // A + B
#define SMEM_BYTES (2 * STAGE_W * 4)     // 73728 B

__global__ __launch_bounds__(256)
void tgemm_k(const float* __restrict__ A, int lda, long long sA,
             const float* __restrict__ B, int ldb, long long sB,
             float*       __restrict__ C, int ldc, long long sC,
             int K,
             const float* __restrict__ bias,
             const float* __restrict__ res,
             float scale, int relu, int causal_skip, int klimit)
{
    const int bm = blockIdx.y * 128;
    const int bn = blockIdx.x * 128;
    if (causal_skip && bn > bm) return;

    extern __shared__ float sm[];
    uint32_t* smu = (uint32_t*)sm;

    const int tid = threadIdx.x;
    const int wid = tid >> 5;
    const int lane = tid & 31;
    const int g   = lane >> 2;           // groupID 0..7
    const int tig = lane & 3;            // thread-in-group 0..3
    const int wm  = wid >> 2;            // 0..1
    const int wn  = wid & 3;             // 0..3

    const long long bz = blockIdx.z;
    A += bz * sA;  B += bz * sB;  C += bz * sC;
    const float* R = res ? res + bz * sC : nullptr;

    int Keff = K;
    if (klimit) { int kl = bm + 128; Keff = (kl < K) ? kl : K; }
    const int KT = Keff >> 5;            // K-tiles of 32

    const float* Abase = A + (long long)bm * lda;
    const float* Bbase = B + (long long)bn * ldb;

    float4 ra[4], rb[4];

#define LDG_TILE(k0) do {                                                      \
    _Pragma("unroll")                                                          \
    for (int t = 0; t < 4; t++) {                                              \
        int c = tid + t * 256;                                                 \
        ra[t] = *(const float4*)(Abase + (long long)(c >> 3) * lda + (k0) + ((c & 7) << 2)); \
        rb[t] = *(const float4*)(Bbase + (long long)(c >> 3) * ldb + (k0) + ((c & 7) << 2)); \
    }                                                                          \
} while (0)

#define STS_TILE(sw) do {                                                      \
    _Pragma("unroll")                                                          \
    for (int t = 0; t < 4; t++) {                                              \
        int c = tid + t * 256;                                                 \
        int w = (sw) + (c >> 3) * PAD + ((c & 7) << 2);                        \
        *(uint4*)&smu[w] = make_uint4(f2tf32(ra[t].x), f2tf32(ra[t].y),        \
                                      f2tf32(ra[t].z), f2tf32(ra[t].w));       \
        *(uint4*)&smu[w + TILE_W] = make_uint4(f2tf32(rb[t].x), f2tf32(rb[t].y),\
                                               f2tf32(rb[t].z), f2tf32(rb[t].w));\
    }                                                                          \
} while (0)

    float acc[4][4][4];
#pragma unroll
    for (int i = 0; i < 4; i++)
#pragma unroll
        for (int j = 0; j < 4; j++)
#pragma unroll
            for (int r = 0; r < 4; r++) acc[i][j][r] = 0.f;

    LDG_TILE(0);

    for (int kt = 0; kt < KT; kt++) {
        const int stage = (kt & 1) * STAGE_W;
        STS_TILE(stage);
        __syncthreads();
        if (kt + 1 < KT) LDG_TILE((kt + 1) << 5);

        const uint32_t* Asp = smu + stage + (wm * 64 + g) * PAD + tig;
        const uint32_t* Bsp = smu + stage + TILE_W + (wn * 32 + g) * PAD + tig;

#pragma unroll
        for (int ks = 0; ks < 4; ks++) {
            uint32_t a[4][4], b[4][2];
#pragma unroll
            for (int mf = 0; mf < 4; mf++) {
                const uint32_t* p = Asp + mf * (16 * PAD) + ks * 8;
                a[mf][0] = p[0];
                a[mf][1] = p[8 * PAD];
                a[mf][2] = p[4];
                a[mf][3] = p[8 * PAD + 4];
            }
#pragma unroll
            for (int nf = 0; nf < 4; nf++) {
                const uint32_t* p = Bsp + nf * (8 * PAD) + ks * 8;
                b[nf][0] = p[0];
                b[nf][1] = p[4];
            }
#pragma unroll
            for (int mf = 0; mf < 4; mf++)
#pragma unroll
                for (int nf = 0; nf < 4; nf++)
                    MMA_TF32(acc[mf][nf], a[mf], b[nf]);
        }
        __syncthreads();
    }

    // epilogue: c0=(g,2tig) c1=(g,2tig+1) c2=(g+8,2tig) c3=(g+8,2tig+1)
#pragma unroll
    for (int mf = 0; mf < 4; mf++) {
        const int m0 = bm + wm * 64 + mf * 16 + g;
#pragma unroll
        for (int nf = 0; nf < 4; nf++) {
            const int n0 = bn + wn * 32 + nf * 8 + 2 * tig;
            float2 v0, v1;
            v0.x = acc[mf][nf][0] * scale; v0.y = acc[mf][nf][1] * scale;
            v1.x = acc[mf][nf][2] * scale; v1.y = acc[mf][nf][3] * scale;
            if (bias) {
                float bx = __ldg(bias + n0), by = __ldg(bias + n0 + 1);
                v0.x += bx; v0.y += by; v1.x += bx; v1.y += by;
            }
            if (R) {
                float2 r0 = *(const float2*)(R + (long long)m0 * ldc + n0);
                float2 r1 = *(const float2*)(R + (long long)(m0 + 8) * ldc + n0);
                v0.x += r0.x; v0.y += r0.y; v1.x += r1.x; v1.y += r1.y;
            }
            if (relu) {
                v0.x = fmaxf(v0.x, 0.f); v0.y = fmaxf(v0.y, 0.f);
                v1.x = fmaxf(v1.x, 0.f); v1.y = fmaxf(v1.y, 0.f);
            }
            *(float2*)(C + (long long)m0 * ldc + n0) = v0;
            *(float2*)(C + (long long)(m0 + 8) * ldc + n0) = v1;
        }
    }
}

// ---------------------------------------------------------------------------
// LayerNorm
// ---------------------------------------------------------------------------
__global__ __launch_bounds__(256)
void ln_k(const float* __restrict__ x, const float* __restrict__ g,
          const float* __restrict__ b, float* __restrict__ y)
{
    const int D = D_MODEL;
    const long long row = blockIdx.x;
    const float* xr = x + row * D;
    float*       yr = y + row * D;
    const int tid = threadIdx.x;

    __shared__ float sh[256];
    float v[8];
    float s = 0.f;
#pragma unroll
    for (int i = 0; i < 8; i++) { v[i] = xr[tid + i * 256]; s += v[i]; }
    sh[tid] = s; __syncthreads();
    for (int o = 128; o > 0; o >>= 1) { if (tid < o) sh[tid] += sh[tid + o]; __syncthreads(); }
    const float mean = sh[0] * (1.f / D);
    __syncthreads();

    s = 0.f;
#pragma unroll
    for (int i = 0; i < 8; i++) { float d = v[i] - mean; s += d * d; }
    sh[tid] = s; __syncthreads();
    for (int o = 128; o > 0; o >>= 1) { if (tid < o) sh[tid] += sh[tid + o]; __syncthreads(); }
    const float r = rsqrtf(sh[0] * (1.f / D) + 1e-5f);

#pragma unroll
    for (int i = 0; i < 8; i++) {
        int j = tid + i * 256;
        yr[j] = (v[i] - mean) * r * __ldg(g + j) + __ldg(b + j);
    }
}

// ---------------------------------------------------------------------------
// RoPE (reference-exact trig-of-trig)
// ---------------------------------------------------------------------------
__global__ __launch_bounds__(256)
void rope_k(const float* __restrict__ qkv, float* __restrict__ Qo, float* __restrict__ Ko)
{
    const int d = D_MODEL, half = D_MODEL / 2;
    const int t = blockIdx.x, b = blockIdx.y;
    const long long rq = ((long long)b * SEQ + t) * (3 * D_MODEL);
    const float* Q = qkv + rq;
    const float* K = qkv + rq + d;
    const long long ro = ((long long)b * SEQ + t) * d;
    const float pos = (float)t;

#pragma unroll
    for (int i = 0; i < 8; i++) {
        int j = threadIdx.x + i * 256;
        int fidx = (j < half) ? j : (j - half);
        float invf = powf(10000.0f, -(float)(2 * fidx) / (float)d);
        float sp = pos * invf;
        float e = (j < half) ? sinf(sp) : cosf(sp);
        float c = cosf(e), s = sinf(e);
        float rqv, rkv;
        if (j < half) { rqv = -Q[2 * j];              rkv = -K[2 * j]; }
        else          { rqv =  Q[2 * (j - half) + 1]; rkv =  K[2 * (j - half) + 1]; }
        Qo[ro + j] = Q[j] * c + rqv * s;
        Ko[ro + j] = K[j] * c - rkv * s;
    }
}

// ---------------------------------------------------------------------------
// V transpose: vt[b, n, s] = qkv[b, s, 2d + n]
// ---------------------------------------------------------------------------
__global__ __launch_bounds__(256)
void vtrans_k(const float* __restrict__ qkv, float* __restrict__ vt)
{
    __shared__ float t[32][33];
    const int b = blockIdx.z;
    const int s0 = blockIdx.y * 32, n0 = blockIdx.x * 32;
    const int x = threadIdx.x, y = threadIdx.y;
#pragma unroll
    for (int i = 0; i < 32; i += 8)
        t[y + i][x] = qkv[((long long)b * SEQ + s0 + y + i) * (3 * D_MODEL) + 2 * D_MODEL + n0 + x];
    __syncthreads();
#pragma unroll
    for (int i = 0; i < 32; i += 8)
        vt[((long long)b * D_MODEL + n0 + y + i) * SEQ + s0 + x] = t[x][y + i];
}

// ---------------------------------------------------------------------------
// Causal softmax (writes only columns < ceil128(q+1), rest never read)
// ---------------------------------------------------------------------------
__global__ __launch_bounds__(256)
void softmax_k(float* __restrict__ P)
{
    const int S = SEQ;
    const int q = blockIdx.x, b = blockIdx.y;
    float* row = P + ((long long)b * S + q) * S;
    const int n = q + 1;
    const int klim = ((q >> 7) + 1) << 7;
    const int tid = threadIdx.x;
    __shared__ float sh[256];

    float v[8];
    float mx = -3.402823e38f;
#pragma unroll
    for (int i = 0; i < 8; i++) {
        int j = tid + i * 256;
        v[i] = (j < n) ? row[j] : -3.402823e38f;
        mx = fmaxf(mx, v[i]);
    }
    sh[tid] = mx; __syncthreads();
    for (int o = 128; o > 0; o >>= 1) { if (tid < o) sh[tid] = fmaxf(sh[tid], sh[tid + o]); __syncthreads(); }
    mx = sh[0]; __syncthreads();

    float sum = 0.f;
#pragma unroll
    for (int i = 0; i < 8; i++) {
        int j = tid + i * 256;
        v[i] = (j < n) ? expf(v[i] - mx) : 0.f;
        sum += v[i];
    }
    sh[tid] = sum; __syncthreads();
    for (int o = 128; o > 0; o >>= 1) { if (tid < o) sh[tid] += sh[tid + o]; __syncthreads(); }
    const float inv = 1.f / sh[0];

#pragma unroll
    for (int i = 0; i < 8; i++) {
        int j = tid + i * 256;
        if (j < klim) row[j] = v[i] * inv;
    }
}

// ---------------------------------------------------------------------------
// Launch
// ---------------------------------------------------------------------------
extern "C" void kernel_launch(void* const* d_in, const int* in_sizes, int n_in,
                              void* d_out, int out_size)
{
    const float* src  = (const float*)d_in[0];
    const float* Wqkv = (const float*)d_in[1];
    const float* bqkv = (const float*)d_in[2];
    const float* Wo   = (const float*)d_in[3];
    const float* bo   = (const float*)d_in[4];
    const float* W1   = (const float*)d_in[5];
    const float* b1   = (const float*)d_in[6];
    const float* W2   = (const float*)d_in[7];
    const float* b2   = (const float*)d_in[8];
    const float* g1   = (const float*)d_in[9];
    const float* be1  = (const float*)d_in[10];
    const float* g2   = (const float*)d_in[11];
    const float* be2  = (const float*)d_in[12];
    float* out = (float*)d_out;

    float *xln, *qkv, *q, *k, *vt, *sc, *attn, *src2, *hln, *h1;
    cudaGetSymbolAddress((void**)&xln,  g_xln);
    cudaGetSymbolAddress((void**)&qkv,  g_qkv);
    cudaGetSymbolAddress((void**)&q,    g_q);
    cudaGetSymbolAddress((void**)&k,    g_k);
    cudaGetSymbolAddress((void**)&vt,   g_vt);
    cudaGetSymbolAddress((void**)&sc,   g_sc);
    cudaGetSymbolAddress((void**)&attn, g_attn);
    cudaGetSymbolAddress((void**)&src2, g_src2);
    cudaGetSymbolAddress((void**)&hln,  g_hln);
    cudaGetSymbolAddress((void**)&h1,   g_h1);

    cudaFuncSetAttribute(tgemm_k, cudaFuncAttributeMaxDynamicSharedMemorySize, SMEM_BYTES);

    const int d = D_MODEL, f = D_FF, S = SEQ, B = BATCH, M = NTOK;
    const long long Sd = (long long)S * d;
    const long long SS = (long long)S * S;
    const float attn_scale = 1.0f / sqrtf((float)d);

    // 1. LN1
    ln_k<<<M, 256>>>(src, g1, be1, xln);
    // 2. QKV projection
    tgemm_k<<<dim3(3 * d / 128, M / 128, 1), 256, SMEM_BYTES>>>(
        xln, d, 0, Wqkv, d, 0, qkv, 3 * d, 0, d, bqkv, nullptr, 1.f, 0, 0, 0);
    // 3. RoPE
    rope_k<<<dim3(S, B), 256>>>(qkv, q, k);
    // 4. V transpose
    vtrans_k<<<dim3(d / 32, S / 32, B), dim3(32, 8)>>>(qkv, vt);
    // 5. scores = scale * Q K^T (causal block skip)
    tgemm_k<<<dim3(S / 128, S / 128, B), 256, SMEM_BYTES>>>(
        q, d, Sd, k, d, Sd, sc, S, SS, d, nullptr, nullptr, attn_scale, 0, 1, 0);
    // 6. softmax
    softmax_k<<<dim3(S, B), 256>>>(sc);
    // 7. attn = P V  (= P @ Vt^T, K truncated per M block)
    tgemm_k<<<dim3(d / 128, S / 128, B), 256, SMEM_BYTES>>>(
        sc, S, SS, vt, S, Sd, attn, d, Sd, S, nullptr, nullptr, 1.f, 0, 0, 1);
    // 8. src2 = xln + attn Wo^T + bo
    tgemm_k<<<dim3(d / 128, M / 128, 1), 256, SMEM_BYTES>>>(
        attn, d, 0, Wo, d, 0, src2, d, 0, d, bo, xln, 1.f, 0, 0, 0);
    // 9. LN2
    ln_k<<<M, 256>>>(src2, g2, be2, hln);
    // 10. h1 = relu(hln W1^T + b1)
    tgemm_k<<<dim3(f / 128, M / 128, 1), 256, SMEM_BYTES>>>(
        hln, d, 0, W1, d, 0, h1, f, 0, d, b1, nullptr, 1.f, 1, 0, 0);
    // 11. out = src2 + h1 W2^T + b2
    tgemm_k<<<dim3(d / 128, M / 128, 1), 256, SMEM_BYTES>>>(
        h1, f, 0, W2, f, 0, out, d, 0, f, b2, src2, 1.f, 0, 0, 0);
}

// round 4
// speedup vs baseline: 3.3219x; 1.0925x over previous
#include <cuda_runtime.h>
#include <math.h>
#include <stdint.h>

#define D_MODEL 2048
#define D_FF    8192
#define BATCH   4
#define SEQ     2048
#define NTOK    (BATCH * SEQ)

// ---------------------------------------------------------------------------
// Scratch
// ---------------------------------------------------------------------------
__device__ float g_xln [(size_t)NTOK * D_MODEL];
__device__ float g_qkv [(size_t)NTOK * 3 * D_MODEL];
__device__ float g_q   [(size_t)NTOK * D_MODEL];
__device__ float g_k   [(size_t)NTOK * D_MODEL];
__device__ float g_vt  [(size_t)NTOK * D_MODEL];      // V^T  [B, d, S]
__device__ float g_sc  [(size_t)BATCH * SEQ * SEQ];
__device__ float g_attn[(size_t)NTOK * D_MODEL];
__device__ float g_src2[(size_t)NTOK * D_MODEL];
__device__ float g_hln [(size_t)NTOK * D_MODEL];
__device__ float g_h1  [(size_t)NTOK * D_FF];

__device__ __forceinline__ uint32_t f2tf32(float f) {
    uint32_t u; asm("cvt.rna.tf32.f32 %0, %1;" : "=r"(u) : "f"(f)); return u;
}

#define MMA_TF32(d, a, b)                                                      \
    asm volatile("mma.sync.aligned.m16n8k8.row.col.f32.tf32.tf32.f32 "         \
        "{%0,%1,%2,%3}, {%4,%5,%6,%7}, {%8,%9}, {%0,%1,%2,%3};"                \
        : "+f"((d)[0]), "+f"((d)[1]), "+f"((d)[2]), "+f"((d)[3])               \
        : "r"((a)[0]), "r"((a)[1]), "r"((a)[2]), "r"((a)[3]),                  \
          "r"((b)[0]), "r"((b)[1]))

// ---------------------------------------------------------------------------
// tf32 mma.sync GEMM: C[M,N] = scale*(A @ B^T) [+bias][+res][relu]
// A:[M,K] fp32 row-major, B:[N,K] fp32 row-major. M,N mult of 128, K of 32.
// CTA 128x128x32, 4 warps (2m x 2n), warp 64x64 (4x8 m16n8k8 frags).
// SMEM rows padded to 36 words -> conflict-free frag LDS.
// ---------------------------------------------------------------------------
#define PAD       36
#define TILE_W    (128 * PAD)            // words per (A or B) tile
#define STAGE_W   (2 * TILE_W)           // A + B
#define SMEM_BYTES (2 * STAGE_W * 4)     // 73728 B
#define NTHREADS  128

__global__ __launch_bounds__(NTHREADS)
void tgemm_k(const float* __restrict__ A, int lda, long long sA,
             const float* __restrict__ B, int ldb, long long sB,
             float*       __restrict__ C, int ldc, long long sC,
             int K,
             const float* __restrict__ bias,
             const float* __restrict__ res,
             float scale, int relu, int causal_skip, int klimit)
{
    const int bm = blockIdx.y * 128;
    const int bn = blockIdx.x * 128;
    if (causal_skip && bn > bm) return;

    extern __shared__ float sm[];
    uint32_t* smu = (uint32_t*)sm;

    const int tid = threadIdx.x;
    const int wid = tid >> 5;
    const int lane = tid & 31;
    const int g   = lane >> 2;           // groupID 0..7
    const int tig = lane & 3;            // thread-in-group 0..3
    const int wm  = wid >> 1;            // 0..1
    const int wn  = wid & 1;             // 0..1

    const long long bz = blockIdx.z;
    A += bz * sA;  B += bz * sB;  C += bz * sC;
    const float* R = res ? res + bz * sC : nullptr;

    int Keff = K;
    if (klimit) { int kl = bm + 128; Keff = (kl < K) ? kl : K; }
    const int KT = Keff >> 5;            // K-tiles of 32

    const float* Abase = A + (long long)bm * lda;
    const float* Bbase = B + (long long)bn * ldb;

    float4 ra[8], rb[8];

#define LDG_TILE(k0) do {                                                      \
    _Pragma("unroll")                                                          \
    for (int t = 0; t < 8; t++) {                                              \
        int c = tid + t * NTHREADS;                                            \
        ra[t] = *(const float4*)(Abase + (long long)(c >> 3) * lda + (k0) + ((c & 7) << 2)); \
        rb[t] = *(const float4*)(Bbase + (long long)(c >> 3) * ldb + (k0) + ((c & 7) << 2)); \
    }                                                                          \
} while (0)

#define STS_TILE(sw) do {                                                      \
    _Pragma("unroll")                                                          \
    for (int t = 0; t < 8; t++) {                                              \
        int c = tid + t * NTHREADS;                                            \
        int w = (sw) + (c >> 3) * PAD + ((c & 7) << 2);                        \
        *(uint4*)&smu[w] = make_uint4(f2tf32(ra[t].x), f2tf32(ra[t].y),        \
                                      f2tf32(ra[t].z), f2tf32(ra[t].w));       \
        *(uint4*)&smu[w + TILE_W] = make_uint4(f2tf32(rb[t].x), f2tf32(rb[t].y),\
                                               f2tf32(rb[t].z), f2tf32(rb[t].w));\
    }                                                                          \
} while (0)

    float acc[4][8][4];
#pragma unroll
    for (int i = 0; i < 4; i++)
#pragma unroll
        for (int j = 0; j < 8; j++)
#pragma unroll
            for (int r = 0; r < 4; r++) acc[i][j][r] = 0.f;

    LDG_TILE(0);

    for (int kt = 0; kt < KT; kt++) {
        const int stage = (kt & 1) * STAGE_W;
        STS_TILE(stage);
        __syncthreads();
        if (kt + 1 < KT) LDG_TILE((kt + 1) << 5);

        const uint32_t* Asp = smu + stage + (wm * 64 + g) * PAD + tig;
        const uint32_t* Bsp = smu + stage + TILE_W + (wn * 64 + g) * PAD + tig;

#pragma unroll
        for (int ks = 0; ks < 4; ks++) {
            uint32_t a[4][4], b[8][2];
#pragma unroll
            for (int mf = 0; mf < 4; mf++) {
                const uint32_t* p = Asp + mf * (16 * PAD) + ks * 8;
                a[mf][0] = p[0];
                a[mf][1] = p[8 * PAD];
                a[mf][2] = p[4];
                a[mf][3] = p[8 * PAD + 4];
            }
#pragma unroll
            for (int nf = 0; nf < 8; nf++) {
                const uint32_t* p = Bsp + nf * (8 * PAD) + ks * 8;
                b[nf][0] = p[0];
                b[nf][1] = p[4];
            }
#pragma unroll
            for (int mf = 0; mf < 4; mf++)
#pragma unroll
                for (int nf = 0; nf < 8; nf++)
                    MMA_TF32(acc[mf][nf], a[mf], b[nf]);
        }
        __syncthreads();
    }

    // epilogue: c0=(g,2tig) c1=(g,2tig+1) c2=(g+8,2tig) c3=(g+8,2tig+1)
#pragma unroll
    for (int mf = 0; mf < 4; mf++) {
        const int m0 = bm + wm * 64 + mf * 16 + g;
#pragma unroll
        for (int nf = 0; nf < 8; nf++) {
            const int n0 = bn + wn * 64 + nf * 8 + 2 * tig;
            float2 v0, v1;
            v0.x = acc[mf][nf][0] * scale; v0.y = acc[mf][nf][1] * scale;
            v1.x = acc[mf][nf][2] * scale; v1.y = acc[mf][nf][3] * scale;
            if (bias) {
                float bx = __ldg(bias + n0), by = __ldg(bias + n0 + 1);
                v0.x += bx; v0.y += by; v1.x += bx; v1.y += by;
            }
            if (R) {
                float2 r0 = *(const float2*)(R + (long long)m0 * ldc + n0);
                float2 r1 = *(const float2*)(R + (long long)(m0 + 8) * ldc + n0);
                v0.x += r0.x; v0.y += r0.y; v1.x += r1.x; v1.y += r1.y;
            }
            if (relu) {
                v0.x = fmaxf(v0.x, 0.f); v0.y = fmaxf(v0.y, 0.f);
                v1.x = fmaxf(v1.x, 0.f); v1.y = fmaxf(v1.y, 0.f);
            }
            *(float2*)(C + (long long)m0 * ldc + n0) = v0;
            *(float2*)(C + (long long)(m0 + 8) * ldc + n0) = v1;
        }
    }
}

// ---------------------------------------------------------------------------
// LayerNorm
// ---------------------------------------------------------------------------
__global__ __launch_bounds__(256)
void ln_k(const float* __restrict__ x, const float* __restrict__ g,
          const float* __restrict__ b, float* __restrict__ y)
{
    const int D = D_MODEL;
    const long long row = blockIdx.x;
    const float* xr = x + row * D;
    float*       yr = y + row * D;
    const int tid = threadIdx.x;

    __shared__ float sh[256];
    float v[8];
    float s = 0.f;
#pragma unroll
    for (int i = 0; i < 8; i++) { v[i] = xr[tid + i * 256]; s += v[i]; }
    sh[tid] = s; __syncthreads();
    for (int o = 128; o > 0; o >>= 1) { if (tid < o) sh[tid] += sh[tid + o]; __syncthreads(); }
    const float mean = sh[0] * (1.f / D);
    __syncthreads();

    s = 0.f;
#pragma unroll
    for (int i = 0; i < 8; i++) { float d = v[i] - mean; s += d * d; }
    sh[tid] = s; __syncthreads();
    for (int o = 128; o > 0; o >>= 1) { if (tid < o) sh[tid] += sh[tid + o]; __syncthreads(); }
    const float r = rsqrtf(sh[0] * (1.f / D) + 1e-5f);

#pragma unroll
    for (int i = 0; i < 8; i++) {
        int j = tid + i * 256;
        yr[j] = (v[i] - mean) * r * __ldg(g + j) + __ldg(b + j);
    }
}

// ---------------------------------------------------------------------------
// RoPE (reference-exact trig-of-trig)
// ---------------------------------------------------------------------------
__global__ __launch_bounds__(256)
void rope_k(const float* __restrict__ qkv, float* __restrict__ Qo, float* __restrict__ Ko)
{
    const int d = D_MODEL, half = D_MODEL / 2;
    const int t = blockIdx.x, b = blockIdx.y;
    const long long rq = ((long long)b * SEQ + t) * (3 * D_MODEL);
    const float* Q = qkv + rq;
    const float* K = qkv + rq + d;
    const long long ro = ((long long)b * SEQ + t) * d;
    const float pos = (float)t;

#pragma unroll
    for (int i = 0; i < 8; i++) {
        int j = threadIdx.x + i * 256;
        int fidx = (j < half) ? j : (j - half);
        float invf = powf(10000.0f, -(float)(2 * fidx) / (float)d);
        float sp = pos * invf;
        float e = (j < half) ? sinf(sp) : cosf(sp);
        float c = cosf(e), s = sinf(e);
        float rqv, rkv;
        if (j < half) { rqv = -Q[2 * j];              rkv = -K[2 * j]; }
        else          { rqv =  Q[2 * (j - half) + 1]; rkv =  K[2 * (j - half) + 1]; }
        Qo[ro + j] = Q[j] * c + rqv * s;
        Ko[ro + j] = K[j] * c - rkv * s;
    }
}

// ---------------------------------------------------------------------------
// V transpose: vt[b, n, s] = qkv[b, s, 2d + n]
// ---------------------------------------------------------------------------
__global__ __launch_bounds__(256)
void vtrans_k(const float* __restrict__ qkv, float* __restrict__ vt)
{
    __shared__ float t[32][33];
    const int b = blockIdx.z;
    const int s0 = blockIdx.y * 32, n0 = blockIdx.x * 32;
    const int x = threadIdx.x, y = threadIdx.y;
#pragma unroll
    for (int i = 0; i < 32; i += 8)
        t[y + i][x] = qkv[((long long)b * SEQ + s0 + y + i) * (3 * D_MODEL) + 2 * D_MODEL + n0 + x];
    __syncthreads();
#pragma unroll
    for (int i = 0; i < 32; i += 8)
        vt[((long long)b * D_MODEL + n0 + y + i) * SEQ + s0 + x] = t[x][y + i];
}

// ---------------------------------------------------------------------------
// Causal softmax (writes only columns < ceil128(q+1), rest never read)
// ---------------------------------------------------------------------------
__global__ __launch_bounds__(256)
void softmax_k(float* __restrict__ P)
{
    const int S = SEQ;
    const int q = blockIdx.x, b = blockIdx.y;
    float* row = P + ((long long)b * S + q) * S;
    const int n = q + 1;
    const int klim = ((q >> 7) + 1) << 7;
    const int tid = threadIdx.x;
    __shared__ float sh[256];

    float v[8];
    float mx = -3.402823e38f;
#pragma unroll
    for (int i = 0; i < 8; i++) {
        int j = tid + i * 256;
        v[i] = (j < n) ? row[j] : -3.402823e38f;
        mx = fmaxf(mx, v[i]);
    }
    sh[tid] = mx; __syncthreads();
    for (int o = 128; o > 0; o >>= 1) { if (tid < o) sh[tid] = fmaxf(sh[tid], sh[tid + o]); __syncthreads(); }
    mx = sh[0]; __syncthreads();

    float sum = 0.f;
#pragma unroll
    for (int i = 0; i < 8; i++) {
        int j = tid + i * 256;
        v[i] = (j < n) ? expf(v[i] - mx) : 0.f;
        sum += v[i];
    }
    sh[tid] = sum; __syncthreads();
    for (int o = 128; o > 0; o >>= 1) { if (tid < o) sh[tid] += sh[tid + o]; __syncthreads(); }
    const float inv = 1.f / sh[0];

#pragma unroll
    for (int i = 0; i < 8; i++) {
        int j = tid + i * 256;
        if (j < klim) row[j] = v[i] * inv;
    }
}

// ---------------------------------------------------------------------------
// Launch
// ---------------------------------------------------------------------------
extern "C" void kernel_launch(void* const* d_in, const int* in_sizes, int n_in,
                              void* d_out, int out_size)
{
    const float* src  = (const float*)d_in[0];
    const float* Wqkv = (const float*)d_in[1];
    const float* bqkv = (const float*)d_in[2];
    const float* Wo   = (const float*)d_in[3];
    const float* bo   = (const float*)d_in[4];
    const float* W1   = (const float*)d_in[5];
    const float* b1   = (const float*)d_in[6];
    const float* W2   = (const float*)d_in[7];
    const float* b2   = (const float*)d_in[8];
    const float* g1   = (const float*)d_in[9];
    const float* be1  = (const float*)d_in[10];
    const float* g2   = (const float*)d_in[11];
    const float* be2  = (const float*)d_in[12];
    float* out = (float*)d_out;

    float *xln, *qkv, *q, *k, *vt, *sc, *attn, *src2, *hln, *h1;
    cudaGetSymbolAddress((void**)&xln,  g_xln);
    cudaGetSymbolAddress((void**)&qkv,  g_qkv);
    cudaGetSymbolAddress((void**)&q,    g_q);
    cudaGetSymbolAddress((void**)&k,    g_k);
    cudaGetSymbolAddress((void**)&vt,   g_vt);
    cudaGetSymbolAddress((void**)&sc,   g_sc);
    cudaGetSymbolAddress((void**)&attn, g_attn);
    cudaGetSymbolAddress((void**)&src2, g_src2);
    cudaGetSymbolAddress((void**)&hln,  g_hln);
    cudaGetSymbolAddress((void**)&h1,   g_h1);

    cudaFuncSetAttribute(tgemm_k, cudaFuncAttributeMaxDynamicSharedMemorySize, SMEM_BYTES);

    const int d = D_MODEL, f = D_FF, S = SEQ, B = BATCH, M = NTOK;
    const long long Sd = (long long)S * d;
    const long long SS = (long long)S * S;
    const float attn_scale = 1.0f / sqrtf((float)d);

    // 1. LN1
    ln_k<<<M, 256>>>(src, g1, be1, xln);
    // 2. QKV projection
    tgemm_k<<<dim3(3 * d / 128, M / 128, 1), NTHREADS, SMEM_BYTES>>>(
        xln, d, 0, Wqkv, d, 0, qkv, 3 * d, 0, d, bqkv, nullptr, 1.f, 0, 0, 0);
    // 3. RoPE
    rope_k<<<dim3(S, B), 256>>>(qkv, q, k);
    // 4. V transpose
    vtrans_k<<<dim3(d / 32, S / 32, B), dim3(32, 8)>>>(qkv, vt);
    // 5. scores = scale * Q K^T (causal block skip)
    tgemm_k<<<dim3(S / 128, S / 128, B), NTHREADS, SMEM_BYTES>>>(
        q, d, Sd, k, d, Sd, sc, S, SS, d, nullptr, nullptr, attn_scale, 0, 1, 0);
    // 6. softmax
    softmax_k<<<dim3(S, B), 256>>>(sc);
    // 7. attn = P V  (= P @ Vt^T, K truncated per M block)
    tgemm_k<<<dim3(d / 128, S / 128, B), NTHREADS, SMEM_BYTES>>>(
        sc, S, SS, vt, S, Sd, attn, d, Sd, S, nullptr, nullptr, 1.f, 0, 0, 1);
    // 8. src2 = xln + attn Wo^T + bo
    tgemm_k<<<dim3(d / 128, M / 128, 1), NTHREADS, SMEM_BYTES>>>(
        attn, d, 0, Wo, d, 0, src2, d, 0, d, bo, xln, 1.f, 0, 0, 0);
    // 9. LN2
    ln_k<<<M, 256>>>(src2, g2, be2, hln);
    // 10. h1 = relu(hln W1^T + b1)
    tgemm_k<<<dim3(f / 128, M / 128, 1), NTHREADS, SMEM_BYTES>>>(
        hln, d, 0, W1, d, 0, h1, f, 0, d, b1, nullptr, 1.f, 1, 0, 0);
    // 11. out = src2 + h1 W2^T + b2
    tgemm_k<<<dim3(d / 128, M / 128, 1), NTHREADS, SMEM_BYTES>>>(
        h1, f, 0, W2, f, 0, out, d, 0, f, b2, src2, 1.f, 0, 0, 0);
}

// round 5
// speedup vs baseline: 3.7345x; 1.1242x over previous
#include <cuda_runtime.h>
#include <math.h>
#include <stdint.h>

#define D_MODEL 2048
#define D_FF    8192
#define BATCH   4
#define SEQ     2048
#define NTOK    (BATCH * SEQ)

// ---------------------------------------------------------------------------
// Scratch
// ---------------------------------------------------------------------------
__device__ float g_xln [(size_t)NTOK * D_MODEL];
__device__ float g_qkv [(size_t)NTOK * 3 * D_MODEL];
__device__ float g_q   [(size_t)NTOK * D_MODEL];
__device__ float g_k   [(size_t)NTOK * D_MODEL];
__device__ float g_vt  [(size_t)NTOK * D_MODEL];      // V^T  [B, d, S]
__device__ float g_sc  [(size_t)BATCH * SEQ * SEQ];
__device__ float g_attn[(size_t)NTOK * D_MODEL];
__device__ float g_src2[(size_t)NTOK * D_MODEL];
__device__ float g_hln [(size_t)NTOK * D_MODEL];
__device__ float g_h1  [(size_t)NTOK * D_FF];
// tf32-rounded weights
__device__ float g_wqkv[(size_t)3 * D_MODEL * D_MODEL];
__device__ float g_wo  [(size_t)D_MODEL * D_MODEL];
__device__ float g_w1  [(size_t)D_FF * D_MODEL];
__device__ float g_w2  [(size_t)D_MODEL * D_FF];

__device__ __forceinline__ uint32_t f2tf32(float f) {
    uint32_t u; asm("cvt.rna.tf32.f32 %0, %1;" : "=r"(u) : "f"(f)); return u;
}
__device__ __forceinline__ float rtf(float f) { return __uint_as_float(f2tf32(f)); }

__device__ __forceinline__ uint32_t smem_u32(const void* p) {
    uint32_t a;
    asm("{ .reg .u64 t; cvta.to.shared.u64 t, %1; cvt.u32.u64 %0, t; }" : "=r"(a) : "l"(p));
    return a;
}

#define MMA_TF32(d, a, b)                                                      \
    asm volatile("mma.sync.aligned.m16n8k8.row.col.f32.tf32.tf32.f32 "         \
        "{%0,%1,%2,%3}, {%4,%5,%6,%7}, {%8,%9}, {%0,%1,%2,%3};"                \
        : "+f"((d)[0]), "+f"((d)[1]), "+f"((d)[2]), "+f"((d)[3])               \
        : "r"((a)[0]), "r"((a)[1]), "r"((a)[2]), "r"((a)[3]),                  \
          "r"((b)[0]), "r"((b)[1]))

#define CP16(dst, src) \
    asm volatile("cp.async.cg.shared.global [%0], [%1], 16;" :: "r"(dst), "l"(src))
#define CP_COMMIT() asm volatile("cp.async.commit_group;" ::: "memory")
#define CP_WAIT(n)  asm volatile("cp.async.wait_group %0;" :: "n"(n) : "memory")

// ---------------------------------------------------------------------------
// tf32 mma.sync GEMM (inputs pre-rounded to tf32 bit patterns):
//   C[M,N] = scale*(A @ B^T) [+bias][+res][relu][round-out]
// CTA 128x128x32, 4 warps (2m x 2n), warp 64x64. 3-stage cp.async pipeline.
// SMEM rows 36 words (144 B) -> conflict-free frag LDS, 16B-aligned cp.async.
// ---------------------------------------------------------------------------
#define PAD       36
#define TILE_W    (128 * PAD)            // words per (A or B) tile
#define TILE_B    (TILE_W * 4)           // 18432 bytes
#define STAGE_W   (2 * TILE_W)
#define STAGE_B   (2 * TILE_B)           // 36864 bytes
#define STAGES    3
#define SMEM_BYTES (STAGES * STAGE_B)    // 110592 B
#define NTHREADS  128

__global__ __launch_bounds__(NTHREADS)
void tgemm_k(const float* __restrict__ A, int lda, long long sA,
             const float* __restrict__ B, int ldb, long long sB,
             float*       __restrict__ C, int ldc, long long sC,
             int K,
             const float* __restrict__ bias,
             const float* __restrict__ res,
             float scale, int relu, int causal_skip, int klimit, int round_out)
{
    const int bm = blockIdx.y * 128;
    const int bn = blockIdx.x * 128;
    if (causal_skip && bn > bm) return;

    extern __shared__ float sm[];
    uint32_t* smu = (uint32_t*)sm;
    const uint32_t sbase = smem_u32(sm);

    const int tid = threadIdx.x;
    const int wid = tid >> 5;
    const int lane = tid & 31;
    const int g   = lane >> 2;
    const int tig = lane & 3;
    const int wm  = wid >> 1;
    const int wn  = wid & 1;

    const long long bz = blockIdx.z;
    A += bz * sA;  B += bz * sB;  C += bz * sC;
    const float* R = res ? res + bz * sC : nullptr;

    int Keff = K;
    if (klimit) { int kl = bm + 128; Keff = (kl < K) ? kl : K; }
    const int KT = Keff >> 5;

    const float* Abase = A + (long long)bm * lda;
    const float* Bbase = B + (long long)bn * ldb;

#define ISSUE(kt_, st_) do {                                                   \
    const int _k0 = (kt_) << 5;                                                \
    const uint32_t _so = (uint32_t)(st_) * STAGE_B;                            \
    _Pragma("unroll")                                                          \
    for (int t = 0; t < 8; t++) {                                              \
        int c = tid + t * NTHREADS;                                            \
        uint32_t w = (uint32_t)(c >> 3) * 144u + (uint32_t)((c & 7) << 4);     \
        CP16(sbase + _so + w,                                                  \
             Abase + (long long)(c >> 3) * lda + _k0 + ((c & 7) << 2));        \
        CP16(sbase + _so + TILE_B + w,                                         \
             Bbase + (long long)(c >> 3) * ldb + _k0 + ((c & 7) << 2));        \
    }                                                                          \
} while (0)

    float acc[4][8][4];
#pragma unroll
    for (int i = 0; i < 4; i++)
#pragma unroll
        for (int j = 0; j < 8; j++)
#pragma unroll
            for (int r = 0; r < 4; r++) acc[i][j][r] = 0.f;

    // prologue: stages 0..STAGES-2
#pragma unroll
    for (int s = 0; s < STAGES - 1; s++) { ISSUE(s, s); CP_COMMIT(); }
    CP_WAIT(STAGES - 2);
    __syncthreads();

    for (int kt = 0; kt < KT; kt++) {
        const int next = kt + STAGES - 1;
        if (next < KT) ISSUE(next, next % STAGES);
        CP_COMMIT();

        const int stage = (kt % STAGES) * STAGE_W;
        const uint32_t* Asp = smu + stage + (wm * 64 + g) * PAD + tig;
        const uint32_t* Bsp = smu + stage + TILE_W + (wn * 64 + g) * PAD + tig;

#pragma unroll
        for (int ks = 0; ks < 4; ks++) {
            uint32_t a[4][4], b[8][2];
#pragma unroll
            for (int mf = 0; mf < 4; mf++) {
                const uint32_t* p = Asp + mf * (16 * PAD) + ks * 8;
                a[mf][0] = p[0];
                a[mf][1] = p[8 * PAD];
                a[mf][2] = p[4];
                a[mf][3] = p[8 * PAD + 4];
            }
#pragma unroll
            for (int nf = 0; nf < 8; nf++) {
                const uint32_t* p = Bsp + nf * (8 * PAD) + ks * 8;
                b[nf][0] = p[0];
                b[nf][1] = p[4];
            }
#pragma unroll
            for (int mf = 0; mf < 4; mf++)
#pragma unroll
                for (int nf = 0; nf < 8; nf++)
                    MMA_TF32(acc[mf][nf], a[mf], b[nf]);
        }
        CP_WAIT(STAGES - 2);
        __syncthreads();
    }

    // epilogue
#pragma unroll
    for (int mf = 0; mf < 4; mf++) {
        const int m0 = bm + wm * 64 + mf * 16 + g;
#pragma unroll
        for (int nf = 0; nf < 8; nf++) {
            const int n0 = bn + wn * 64 + nf * 8 + 2 * tig;
            float2 v0, v1;
            v0.x = acc[mf][nf][0] * scale; v0.y = acc[mf][nf][1] * scale;
            v1.x = acc[mf][nf][2] * scale; v1.y = acc[mf][nf][3] * scale;
            if (bias) {
                float bx = __ldg(bias + n0), by = __ldg(bias + n0 + 1);
                v0.x += bx; v0.y += by; v1.x += bx; v1.y += by;
            }
            if (R) {
                float2 r0 = *(const float2*)(R + (long long)m0 * ldc + n0);
                float2 r1 = *(const float2*)(R + (long long)(m0 + 8) * ldc + n0);
                v0.x += r0.x; v0.y += r0.y; v1.x += r1.x; v1.y += r1.y;
            }
            if (relu) {
                v0.x = fmaxf(v0.x, 0.f); v0.y = fmaxf(v0.y, 0.f);
                v1.x = fmaxf(v1.x, 0.f); v1.y = fmaxf(v1.y, 0.f);
            }
            if (round_out) {
                v0.x = rtf(v0.x); v0.y = rtf(v0.y);
                v1.x = rtf(v1.x); v1.y = rtf(v1.y);
            }
            *(float2*)(C + (long long)m0 * ldc + n0) = v0;
            *(float2*)(C + (long long)(m0 + 8) * ldc + n0) = v1;
        }
    }
}

// ---------------------------------------------------------------------------
// tf32 rounding copy (for weights)
// ---------------------------------------------------------------------------
__global__ __launch_bounds__(256)
void round_k(const float* __restrict__ x, float* __restrict__ y, long long n4)
{
    long long i = (long long)blockIdx.x * 256 + threadIdx.x;
    if (i < n4) {
        float4 v = ((const float4*)x)[i];
        v.x = rtf(v.x); v.y = rtf(v.y); v.z = rtf(v.z); v.w = rtf(v.w);
        ((float4*)y)[i] = v;
    }
}

// ---------------------------------------------------------------------------
// LayerNorm (stores tf32-rounded)
// ---------------------------------------------------------------------------
__global__ __launch_bounds__(256)
void ln_k(const float* __restrict__ x, const float* __restrict__ g,
          const float* __restrict__ b, float* __restrict__ y)
{
    const int D = D_MODEL;
    const long long row = blockIdx.x;
    const float* xr = x + row * D;
    float*       yr = y + row * D;
    const int tid = threadIdx.x;

    __shared__ float sh[256];
    float v[8];
    float s = 0.f;
#pragma unroll
    for (int i = 0; i < 8; i++) { v[i] = xr[tid + i * 256]; s += v[i]; }
    sh[tid] = s; __syncthreads();
    for (int o = 128; o > 0; o >>= 1) { if (tid < o) sh[tid] += sh[tid + o]; __syncthreads(); }
    const float mean = sh[0] * (1.f / D);
    __syncthreads();

    s = 0.f;
#pragma unroll
    for (int i = 0; i < 8; i++) { float d = v[i] - mean; s += d * d; }
    sh[tid] = s; __syncthreads();
    for (int o = 128; o > 0; o >>= 1) { if (tid < o) sh[tid] += sh[tid + o]; __syncthreads(); }
    const float r = rsqrtf(sh[0] * (1.f / D) + 1e-5f);

#pragma unroll
    for (int i = 0; i < 8; i++) {
        int j = tid + i * 256;
        yr[j] = rtf((v[i] - mean) * r * __ldg(g + j) + __ldg(b + j));
    }
}

// ---------------------------------------------------------------------------
// RoPE (reference-exact trig-of-trig; stores tf32-rounded)
// ---------------------------------------------------------------------------
__global__ __launch_bounds__(256)
void rope_k(const float* __restrict__ qkv, float* __restrict__ Qo, float* __restrict__ Ko)
{
    const int d = D_MODEL, half = D_MODEL / 2;
    const int t = blockIdx.x, b = blockIdx.y;
    const long long rq = ((long long)b * SEQ + t) * (3 * D_MODEL);
    const float* Q = qkv + rq;
    const float* K = qkv + rq + d;
    const long long ro = ((long long)b * SEQ + t) * d;
    const float pos = (float)t;

#pragma unroll
    for (int i = 0; i < 8; i++) {
        int j = threadIdx.x + i * 256;
        int fidx = (j < half) ? j : (j - half);
        float invf = powf(10000.0f, -(float)(2 * fidx) / (float)d);
        float sp = pos * invf;
        float e = (j < half) ? sinf(sp) : cosf(sp);
        float c = cosf(e), s = sinf(e);
        float rqv, rkv;
        if (j < half) { rqv = -Q[2 * j];              rkv = -K[2 * j]; }
        else          { rqv =  Q[2 * (j - half) + 1]; rkv =  K[2 * (j - half) + 1]; }
        Qo[ro + j] = rtf(Q[j] * c + rqv * s);
        Ko[ro + j] = rtf(K[j] * c - rkv * s);
    }
}

// ---------------------------------------------------------------------------
// V transpose (stores tf32-rounded): vt[b, n, s] = qkv[b, s, 2d + n]
// ---------------------------------------------------------------------------
__global__ __launch_bounds__(256)
void vtrans_k(const float* __restrict__ qkv, float* __restrict__ vt)
{
    __shared__ float t[32][33];
    const int b = blockIdx.z;
    const int s0 = blockIdx.y * 32, n0 = blockIdx.x * 32;
    const int x = threadIdx.x, y = threadIdx.y;
#pragma unroll
    for (int i = 0; i < 32; i += 8)
        t[y + i][x] = qkv[((long long)b * SEQ + s0 + y + i) * (3 * D_MODEL) + 2 * D_MODEL + n0 + x];
    __syncthreads();
#pragma unroll
    for (int i = 0; i < 32; i += 8)
        vt[((long long)b * D_MODEL + n0 + y + i) * SEQ + s0 + x] = rtf(t[x][y + i]);
}

// ---------------------------------------------------------------------------
// Causal softmax (stores tf32-rounded; writes only cols < ceil128(q+1))
// ---------------------------------------------------------------------------
__global__ __launch_bounds__(256)
void softmax_k(float* __restrict__ P)
{
    const int S = SEQ;
    const int q = blockIdx.x, b = blockIdx.y;
    float* row = P + ((long long)b * S + q) * S;
    const int n = q + 1;
    const int klim = ((q >> 7) + 1) << 7;
    const int tid = threadIdx.x;
    __shared__ float sh[256];

    float v[8];
    float mx = -3.402823e38f;
#pragma unroll
    for (int i = 0; i < 8; i++) {
        int j = tid + i * 256;
        v[i] = (j < n) ? row[j] : -3.402823e38f;
        mx = fmaxf(mx, v[i]);
    }
    sh[tid] = mx; __syncthreads();
    for (int o = 128; o > 0; o >>= 1) { if (tid < o) sh[tid] = fmaxf(sh[tid], sh[tid + o]); __syncthreads(); }
    mx = sh[0]; __syncthreads();

    float sum = 0.f;
#pragma unroll
    for (int i = 0; i < 8; i++) {
        int j = tid + i * 256;
        v[i] = (j < n) ? expf(v[i] - mx) : 0.f;
        sum += v[i];
    }
    sh[tid] = sum; __syncthreads();
    for (int o = 128; o > 0; o >>= 1) { if (tid < o) sh[tid] += sh[tid + o]; __syncthreads(); }
    const float inv = 1.f / sh[0];

#pragma unroll
    for (int i = 0; i < 8; i++) {
        int j = tid + i * 256;
        if (j < klim) row[j] = rtf(v[i] * inv);
    }
}

// ---------------------------------------------------------------------------
// Launch
// ---------------------------------------------------------------------------
extern "C" void kernel_launch(void* const* d_in, const int* in_sizes, int n_in,
                              void* d_out, int out_size)
{
    const float* src  = (const float*)d_in[0];
    const float* Wqkv = (const float*)d_in[1];
    const float* bqkv = (const float*)d_in[2];
    const float* Wo   = (const float*)d_in[3];
    const float* bo   = (const float*)d_in[4];
    const float* W1   = (const float*)d_in[5];
    const float* b1   = (const float*)d_in[6];
    const float* W2   = (const float*)d_in[7];
    const float* b2   = (const float*)d_in[8];
    const float* g1   = (const float*)d_in[9];
    const float* be1  = (const float*)d_in[10];
    const float* g2   = (const float*)d_in[11];
    const float* be2  = (const float*)d_in[12];
    float* out = (float*)d_out;

    float *xln, *qkv, *q, *k, *vt, *sc, *attn, *src2, *hln, *h1;
    float *wqkv, *wo, *w1, *w2;
    cudaGetSymbolAddress((void**)&xln,  g_xln);
    cudaGetSymbolAddress((void**)&qkv,  g_qkv);
    cudaGetSymbolAddress((void**)&q,    g_q);
    cudaGetSymbolAddress((void**)&k,    g_k);
    cudaGetSymbolAddress((void**)&vt,   g_vt);
    cudaGetSymbolAddress((void**)&sc,   g_sc);
    cudaGetSymbolAddress((void**)&attn, g_attn);
    cudaGetSymbolAddress((void**)&src2, g_src2);
    cudaGetSymbolAddress((void**)&hln,  g_hln);
    cudaGetSymbolAddress((void**)&h1,   g_h1);
    cudaGetSymbolAddress((void**)&wqkv, g_wqkv);
    cudaGetSymbolAddress((void**)&wo,   g_wo);
    cudaGetSymbolAddress((void**)&w1,   g_w1);
    cudaGetSymbolAddress((void**)&w2,   g_w2);

    cudaFuncSetAttribute(tgemm_k, cudaFuncAttributeMaxDynamicSharedMemorySize, SMEM_BYTES);

    const int d = D_MODEL, f = D_FF, S = SEQ, B = BATCH, M = NTOK;
    const long long Sd = (long long)S * d;
    const long long SS = (long long)S * S;
    const float attn_scale = 1.0f / sqrtf((float)d);

    // 0. round weights to tf32
    {
        long long n4;
        n4 = (long long)3 * d * d / 4; round_k<<<(unsigned)((n4 + 255) / 256), 256>>>(Wqkv, wqkv, n4);
        n4 = (long long)d * d / 4;     round_k<<<(unsigned)((n4 + 255) / 256), 256>>>(Wo,   wo,   n4);
        n4 = (long long)f * d / 4;     round_k<<<(unsigned)((n4 + 255) / 256), 256>>>(W1,   w1,   n4);
        n4 = (long long)d * f / 4;     round_k<<<(unsigned)((n4 + 255) / 256), 256>>>(W2,   w2,   n4);
    }
    // 1. LN1 (rounded output; also residual base)
    ln_k<<<M, 256>>>(src, g1, be1, xln);
    // 2. QKV projection
    tgemm_k<<<dim3(3 * d / 128, M / 128, 1), NTHREADS, SMEM_BYTES>>>(
        xln, d, 0, wqkv, d, 0, qkv, 3 * d, 0, d, bqkv, nullptr, 1.f, 0, 0, 0, 0);
    // 3. RoPE
    rope_k<<<dim3(S, B), 256>>>(qkv, q, k);
    // 4. V transpose
    vtrans_k<<<dim3(d / 32, S / 32, B), dim3(32, 8)>>>(qkv, vt);
    // 5. scores = scale * Q K^T (causal block skip)
    tgemm_k<<<dim3(S / 128, S / 128, B), NTHREADS, SMEM_BYTES>>>(
        q, d, Sd, k, d, Sd, sc, S, SS, d, nullptr, nullptr, attn_scale, 0, 1, 0, 0);
    // 6. softmax
    softmax_k<<<dim3(S, B), 256>>>(sc);
    // 7. attn = P V (K truncated per M block; rounded output)
    tgemm_k<<<dim3(d / 128, S / 128, B), NTHREADS, SMEM_BYTES>>>(
        sc, S, SS, vt, S, Sd, attn, d, Sd, S, nullptr, nullptr, 1.f, 0, 0, 1, 1);
    // 8. src2 = xln + attn Wo^T + bo
    tgemm_k<<<dim3(d / 128, M / 128, 1), NTHREADS, SMEM_BYTES>>>(
        attn, d, 0, wo, d, 0, src2, d, 0, d, bo, xln, 1.f, 0, 0, 0, 0);
    // 9. LN2 (rounded output)
    ln_k<<<M, 256>>>(src2, g2, be2, hln);
    // 10. h1 = relu(hln W1^T + b1) (rounded output)
    tgemm_k<<<dim3(f / 128, M / 128, 1), NTHREADS, SMEM_BYTES>>>(
        hln, d, 0, w1, d, 0, h1, f, 0, d, b1, nullptr, 1.f, 1, 0, 0, 1);
    // 11. out = src2 + h1 W2^T + b2
    tgemm_k<<<dim3(d / 128, M / 128, 1), NTHREADS, SMEM_BYTES>>>(
        h1, f, 0, w2, f, 0, out, d, 0, f, b2, src2, 1.f, 0, 0, 0, 0);
}

// round 7
// speedup vs baseline: 6.0135x; 1.6103x over previous
#include <cuda_runtime.h>
#include <cuda_fp16.h>
#include <math.h>
#include <stdint.h>

#define D_MODEL 2048
#define D_FF    8192
#define BATCH   4
#define SEQ     2048
#define NTOK    (BATCH * SEQ)

// ---------------------------------------------------------------------------
// Scratch
// ---------------------------------------------------------------------------
__device__ float  g_xln [(size_t)NTOK * D_MODEL];        // LN1 out fp32 (residual)
__device__ float  g_qkv [(size_t)NTOK * 3 * D_MODEL];    // QKV fp32
__device__ float  g_sc  [(size_t)BATCH * SEQ * SEQ];     // scores fp32
__device__ float  g_src2[(size_t)NTOK * D_MODEL];        // post-attn residual fp32
__device__ float  g_hln [(size_t)NTOK * D_MODEL];        // LN2 fp32 (unused sink)
__device__ __half g_xln_h[(size_t)NTOK * D_MODEL];
__device__ __half g_q_h [(size_t)NTOK * D_MODEL];
__device__ __half g_k_h [(size_t)NTOK * D_MODEL];
__device__ __half g_vt_h[(size_t)NTOK * D_MODEL];        // V^T [B, d, S]
__device__ __half g_p_h [(size_t)BATCH * SEQ * SEQ];     // probs half
__device__ __half g_at_h[(size_t)NTOK * D_MODEL];        // attn half
__device__ __half g_hln_h[(size_t)NTOK * D_MODEL];
__device__ __half g_h1_h[(size_t)NTOK * D_FF];
__device__ __half g_wqkv[(size_t)3 * D_MODEL * D_MODEL];
__device__ __half g_wo  [(size_t)D_MODEL * D_MODEL];
__device__ __half g_w1  [(size_t)D_FF * D_MODEL];
__device__ __half g_w2  [(size_t)D_MODEL * D_FF];

__device__ __forceinline__ uint32_t smem_u32(const void* p) {
    uint32_t a;
    asm("{ .reg .u64 t; cvta.to.shared.u64 t, %1; cvt.u32.u64 %0, t; }" : "=r"(a) : "l"(p));
    return a;
}

#define MMA_F16(d, a, b)                                                       \
    asm volatile("mma.sync.aligned.m16n8k16.row.col.f32.f16.f16.f32 "          \
        "{%0,%1,%2,%3}, {%4,%5,%6,%7}, {%8,%9}, {%0,%1,%2,%3};"                \
        : "+f"((d)[0]), "+f"((d)[1]), "+f"((d)[2]), "+f"((d)[3])               \
        : "r"((a)[0]), "r"((a)[1]), "r"((a)[2]), "r"((a)[3]),                  \
          "r"((b)[0]), "r"((b)[1]))

#define CP16(dst, src) \
    asm volatile("cp.async.cg.shared.global [%0], [%1], 16;" :: "r"(dst), "l"(src))
#define CP_COMMIT() asm volatile("cp.async.commit_group;" ::: "memory")
#define CP_WAIT(n)  asm volatile("cp.async.wait_group %0;" :: "n"(n) : "memory")

// ---------------------------------------------------------------------------
// fp16 mma GEMM: C[M,N] = scale*(A @ B^T) [+bias][+res][relu]
// A:[M,K] half row-major, B:[N,K] half row-major. M,N mult 128, K mult 32.
// CTA 128x128x32, 4 warps (2x2), warp 64x64, m16n8k16. 3-stage cp.async.
// SMEM row pitch 40 halves (80 B) -> conflict-free frag LDS, 16B cp.async.
// ---------------------------------------------------------------------------
#define PITCH_W   20                     // words per smem row (40 halves)
#define TILE_W    (128 * PITCH_W)        // 2560 words
#define TILE_B    (TILE_W * 4)           // 10240 bytes
#define STAGE_W   (2 * TILE_W)
#define STAGE_B   (2 * TILE_B)           // 20480 bytes
#define STAGES    3
#define SMEM_BYTES (STAGES * STAGE_B)    // 61440 B
#define NTHREADS  128

__global__ __launch_bounds__(NTHREADS)
void hgemm_k(const __half* __restrict__ A, int lda, long long sA,
             const __half* __restrict__ B, int ldb, long long sB,
             void*         __restrict__ Cv, int ldc, long long sC,
             int K,
             const float* __restrict__ bias,
             const float* __restrict__ res,
             float scale, int relu, int causal_skip, int klimit, int half_out)
{
    const int bm = blockIdx.y * 128;
    const int bn = blockIdx.x * 128;
    if (causal_skip && bn > bm) return;

    extern __shared__ float sm[];
    uint32_t* smu = (uint32_t*)sm;
    const uint32_t sbase = smem_u32(sm);

    const int tid = threadIdx.x;
    const int wid = tid >> 5;
    const int lane = tid & 31;
    const int g   = lane >> 2;
    const int tig = lane & 3;
    const int wm  = wid >> 1;
    const int wn  = wid & 1;

    const long long bz = blockIdx.z;
    A += bz * sA;  B += bz * sB;
    const float* R = res ? res + bz * sC : nullptr;

    int Keff = K;
    if (klimit) { int kl = bm + 128; Keff = (kl < K) ? kl : K; }
    const int KT = Keff >> 5;

    const __half* Abase = A + (long long)bm * lda;
    const __half* Bbase = B + (long long)bn * ldb;

#define ISSUE(kt_, st_) do {                                                   \
    const int _k0 = (kt_) << 5;                                                \
    const uint32_t _so = (uint32_t)(st_) * STAGE_B;                            \
    _Pragma("unroll")                                                          \
    for (int t = 0; t < 4; t++) {                                              \
        int c = tid + t * NTHREADS;                                            \
        int row = c >> 2, chk = c & 3;                                         \
        uint32_t w = (uint32_t)row * 80u + (uint32_t)(chk << 4);               \
        CP16(sbase + _so + w,          Abase + (long long)row * lda + _k0 + (chk << 3)); \
        CP16(sbase + _so + TILE_B + w, Bbase + (long long)row * ldb + _k0 + (chk << 3)); \
    }                                                                          \
} while (0)

    float acc[4][8][4];
#pragma unroll
    for (int i = 0; i < 4; i++)
#pragma unroll
        for (int j = 0; j < 8; j++)
#pragma unroll
            for (int r = 0; r < 4; r++) acc[i][j][r] = 0.f;

#pragma unroll
    for (int s = 0; s < STAGES - 1; s++) { ISSUE(s, s); CP_COMMIT(); }
    CP_WAIT(STAGES - 2);
    __syncthreads();

    for (int kt = 0; kt < KT; kt++) {
        const int next = kt + STAGES - 1;
        if (next < KT) ISSUE(next, next % STAGES);
        CP_COMMIT();

        const int stage = (kt % STAGES) * STAGE_W;
        const uint32_t* Asp = smu + stage + (wm * 64 + g) * PITCH_W + tig;
        const uint32_t* Bsp = smu + stage + TILE_W + (wn * 64 + g) * PITCH_W + tig;

#pragma unroll
        for (int ks = 0; ks < 2; ks++) {
            uint32_t a[4][4], b[8][2];
#pragma unroll
            for (int mf = 0; mf < 4; mf++) {
                const uint32_t* p = Asp + mf * (16 * PITCH_W) + ks * 8;
                a[mf][0] = p[0];
                a[mf][1] = p[8 * PITCH_W];
                a[mf][2] = p[4];
                a[mf][3] = p[8 * PITCH_W + 4];
            }
#pragma unroll
            for (int nf = 0; nf < 8; nf++) {
                const uint32_t* p = Bsp + nf * (8 * PITCH_W) + ks * 8;
                b[nf][0] = p[0];
                b[nf][1] = p[4];
            }
#pragma unroll
            for (int mf = 0; mf < 4; mf++)
#pragma unroll
                for (int nf = 0; nf < 8; nf++)
                    MMA_F16(acc[mf][nf], a[mf], b[nf]);
        }
        CP_WAIT(STAGES - 2);
        __syncthreads();
    }

    // epilogue: c0=(g,2tig) c1=(g,2tig+1) c2=(g+8,2tig) c3=(g+8,2tig+1)
    float*  Cf = (float*)Cv  + bz * sC;
    __half* Ch = (__half*)Cv + bz * sC;
#pragma unroll
    for (int mf = 0; mf < 4; mf++) {
        const int m0 = bm + wm * 64 + mf * 16 + g;
#pragma unroll
        for (int nf = 0; nf < 8; nf++) {
            const int n0 = bn + wn * 64 + nf * 8 + 2 * tig;
            float2 v0, v1;
            v0.x = acc[mf][nf][0] * scale; v0.y = acc[mf][nf][1] * scale;
            v1.x = acc[mf][nf][2] * scale; v1.y = acc[mf][nf][3] * scale;
            if (bias) {
                float bx = __ldg(bias + n0), by = __ldg(bias + n0 + 1);
                v0.x += bx; v0.y += by; v1.x += bx; v1.y += by;
            }
            if (R) {
                float2 r0 = *(const float2*)(R + (long long)m0 * ldc + n0);
                float2 r1 = *(const float2*)(R + (long long)(m0 + 8) * ldc + n0);
                v0.x += r0.x; v0.y += r0.y; v1.x += r1.x; v1.y += r1.y;
            }
            if (relu) {
                v0.x = fmaxf(v0.x, 0.f); v0.y = fmaxf(v0.y, 0.f);
                v1.x = fmaxf(v1.x, 0.f); v1.y = fmaxf(v1.y, 0.f);
            }
            if (half_out) {
                *(__half2*)(Ch + (long long)m0 * ldc + n0)       = __floats2half2_rn(v0.x, v0.y);
                *(__half2*)(Ch + (long long)(m0 + 8) * ldc + n0) = __floats2half2_rn(v1.x, v1.y);
            } else {
                *(float2*)(Cf + (long long)m0 * ldc + n0)       = v0;
                *(float2*)(Cf + (long long)(m0 + 8) * ldc + n0) = v1;
            }
        }
    }
}

// ---------------------------------------------------------------------------
// fp32 -> fp16 conversion (weights)
// ---------------------------------------------------------------------------
__global__ __launch_bounds__(256)
void cvt_k(const float* __restrict__ x, __half* __restrict__ y, long long n4)
{
    long long i = (long long)blockIdx.x * 256 + threadIdx.x;
    if (i < n4) {
        float4 v = ((const float4*)x)[i];
        __half2 h0 = __floats2half2_rn(v.x, v.y);
        __half2 h1 = __floats2half2_rn(v.z, v.w);
        ((uint2*)y)[i] = make_uint2(*(uint32_t*)&h0, *(uint32_t*)&h1);
    }
}

// ---------------------------------------------------------------------------
// LayerNorm: fp32 out (residual) + half out (GEMM input)
// ---------------------------------------------------------------------------
__global__ __launch_bounds__(256)
void ln_k(const float* __restrict__ x, const float* __restrict__ g,
          const float* __restrict__ b, float* __restrict__ y, __half* __restrict__ yh)
{
    const int D = D_MODEL;
    const long long row = blockIdx.x;
    const float* xr = x + row * D;
    float*       yr = y + row * D;
    __half*      hr = yh + row * D;
    const int tid = threadIdx.x;

    __shared__ float sh[256];
    float v[8];
    float s = 0.f;
#pragma unroll
    for (int i = 0; i < 8; i++) { v[i] = xr[tid + i * 256]; s += v[i]; }
    sh[tid] = s; __syncthreads();
    for (int o = 128; o > 0; o >>= 1) { if (tid < o) sh[tid] += sh[tid + o]; __syncthreads(); }
    const float mean = sh[0] * (1.f / D);
    __syncthreads();

    s = 0.f;
#pragma unroll
    for (int i = 0; i < 8; i++) { float d = v[i] - mean; s += d * d; }
    sh[tid] = s; __syncthreads();
    for (int o = 128; o > 0; o >>= 1) { if (tid < o) sh[tid] += sh[tid + o]; __syncthreads(); }
    const float r = rsqrtf(sh[0] * (1.f / D) + 1e-5f);

#pragma unroll
    for (int i = 0; i < 8; i++) {
        int j = tid + i * 256;
        float o = (v[i] - mean) * r * __ldg(g + j) + __ldg(b + j);
        yr[j] = o;
        hr[j] = __float2half_rn(o);
    }
}

// ---------------------------------------------------------------------------
// RoPE (reference-exact trig-of-trig), half outputs
// ---------------------------------------------------------------------------
__global__ __launch_bounds__(256)
void rope_k(const float* __restrict__ qkv, __half* __restrict__ Qo, __half* __restrict__ Ko)
{
    const int d = D_MODEL, half = D_MODEL / 2;
    const int t = blockIdx.x, b = blockIdx.y;
    const long long rq = ((long long)b * SEQ + t) * (3 * D_MODEL);
    const float* Q = qkv + rq;
    const float* K = qkv + rq + d;
    const long long ro = ((long long)b * SEQ + t) * d;
    const float pos = (float)t;

#pragma unroll
    for (int i = 0; i < 8; i++) {
        int j = threadIdx.x + i * 256;
        int fidx = (j < half) ? j : (j - half);
        float invf = powf(10000.0f, -(float)(2 * fidx) / (float)d);
        float sp = pos * invf;
        float e = (j < half) ? sinf(sp) : cosf(sp);
        float c = cosf(e), s = sinf(e);
        float rqv, rkv;
        if (j < half) { rqv = -Q[2 * j];              rkv = -K[2 * j]; }
        else          { rqv =  Q[2 * (j - half) + 1]; rkv =  K[2 * (j - half) + 1]; }
        Qo[ro + j] = __float2half_rn(Q[j] * c + rqv * s);
        Ko[ro + j] = __float2half_rn(K[j] * c - rkv * s);
    }
}

// ---------------------------------------------------------------------------
// V transpose -> half: vt[b, n, s] = qkv[b, s, 2d + n]
// ---------------------------------------------------------------------------
__global__ __launch_bounds__(256)
void vtrans_k(const float* __restrict__ qkv, __half* __restrict__ vt)
{
    __shared__ float t[32][33];
    const int b = blockIdx.z;
    const int s0 = blockIdx.y * 32, n0 = blockIdx.x * 32;
    const int x = threadIdx.x, y = threadIdx.y;
#pragma unroll
    for (int i = 0; i < 32; i += 8)
        t[y + i][x] = qkv[((long long)b * SEQ + s0 + y + i) * (3 * D_MODEL) + 2 * D_MODEL + n0 + x];
    __syncthreads();
#pragma unroll
    for (int i = 0; i < 32; i += 8)
        vt[((long long)b * D_MODEL + n0 + y + i) * SEQ + s0 + x] = __float2half_rn(t[x][y + i]);
}

// ---------------------------------------------------------------------------
// Causal softmax: fp32 scores in, half probs out (cols < ceil128(q+1))
// ---------------------------------------------------------------------------
__global__ __launch_bounds__(256)
void softmax_k(const float* __restrict__ S_, __half* __restrict__ P)
{
    const int S = SEQ;
    const int q = blockIdx.x, b = blockIdx.y;
    const float* row = S_ + ((long long)b * S + q) * S;
    __half* prow = P + ((long long)b * S + q) * S;
    const int n = q + 1;
    const int klim = ((q >> 7) + 1) << 7;
    const int tid = threadIdx.x;
    __shared__ float sh[256];

    float v[8];
    float mx = -3.402823e38f;
#pragma unroll
    for (int i = 0; i < 8; i++) {
        int j = tid + i * 256;
        v[i] = (j < n) ? row[j] : -3.402823e38f;
        mx = fmaxf(mx, v[i]);
    }
    sh[tid] = mx; __syncthreads();
    for (int o = 128; o > 0; o >>= 1) { if (tid < o) sh[tid] = fmaxf(sh[tid], sh[tid + o]); __syncthreads(); }
    mx = sh[0]; __syncthreads();

    float sum = 0.f;
#pragma unroll
    for (int i = 0; i < 8; i++) {
        int j = tid + i * 256;
        v[i] = (j < n) ? expf(v[i] - mx) : 0.f;
        sum += v[i];
    }
    sh[tid] = sum; __syncthreads();
    for (int o = 128; o > 0; o >>= 1) { if (tid < o) sh[tid] += sh[tid + o]; __syncthreads(); }
    const float inv = 1.f / sh[0];

#pragma unroll
    for (int i = 0; i < 8; i++) {
        int j = tid + i * 256;
        if (j < klim) prow[j] = __float2half_rn(v[i] * inv);
    }
}

// ---------------------------------------------------------------------------
// Launch
// ---------------------------------------------------------------------------
extern "C" void kernel_launch(void* const* d_in, const int* in_sizes, int n_in,
                              void* d_out, int out_size)
{
    const float* src  = (const float*)d_in[0];
    const float* Wqkv = (const float*)d_in[1];
    const float* bqkv = (const float*)d_in[2];
    const float* Wo   = (const float*)d_in[3];
    const float* bo   = (const float*)d_in[4];
    const float* W1   = (const float*)d_in[5];
    const float* b1   = (const float*)d_in[6];
    const float* W2   = (const float*)d_in[7];
    const float* b2   = (const float*)d_in[8];
    const float* g1   = (const float*)d_in[9];
    const float* be1  = (const float*)d_in[10];
    const float* g2   = (const float*)d_in[11];
    const float* be2  = (const float*)d_in[12];
    float* out = (float*)d_out;

    float *xln, *qkv, *sc, *src2, *hln;
    __half *xln_h, *q_h, *k_h, *vt_h, *p_h, *at_h, *hln_h, *h1_h;
    __half *wqkv, *wo, *w1, *w2;
    cudaGetSymbolAddress((void**)&xln,   g_xln);
    cudaGetSymbolAddress((void**)&qkv,   g_qkv);
    cudaGetSymbolAddress((void**)&sc,    g_sc);
    cudaGetSymbolAddress((void**)&src2,  g_src2);
    cudaGetSymbolAddress((void**)&hln,   g_hln);
    cudaGetSymbolAddress((void**)&xln_h, g_xln_h);
    cudaGetSymbolAddress((void**)&q_h,   g_q_h);
    cudaGetSymbolAddress((void**)&k_h,   g_k_h);
    cudaGetSymbolAddress((void**)&vt_h,  g_vt_h);
    cudaGetSymbolAddress((void**)&p_h,   g_p_h);
    cudaGetSymbolAddress((void**)&at_h,  g_at_h);
    cudaGetSymbolAddress((void**)&hln_h, g_hln_h);
    cudaGetSymbolAddress((void**)&h1_h,  g_h1_h);
    cudaGetSymbolAddress((void**)&wqkv,  g_wqkv);
    cudaGetSymbolAddress((void**)&wo,    g_wo);
    cudaGetSymbolAddress((void**)&w1,    g_w1);
    cudaGetSymbolAddress((void**)&w2,    g_w2);

    cudaFuncSetAttribute(hgemm_k, cudaFuncAttributeMaxDynamicSharedMemorySize, SMEM_BYTES);

    const int d = D_MODEL, f = D_FF, S = SEQ, B = BATCH, M = NTOK;
    const long long Sd = (long long)S * d;
    const long long SS = (long long)S * S;
    const float attn_scale = 1.0f / sqrtf((float)d);

    // 0. convert weights to fp16
    {
        long long n4;
        n4 = (long long)3 * d * d / 4; cvt_k<<<(unsigned)((n4 + 255) / 256), 256>>>(Wqkv, wqkv, n4);
        n4 = (long long)d * d / 4;     cvt_k<<<(unsigned)((n4 + 255) / 256), 256>>>(Wo,   wo,   n4);
        n4 = (long long)f * d / 4;     cvt_k<<<(unsigned)((n4 + 255) / 256), 256>>>(W1,   w1,   n4);
        n4 = (long long)d * f / 4;     cvt_k<<<(unsigned)((n4 + 255) / 256), 256>>>(W2,   w2,   n4);
    }
    // 1. LN1 (fp32 residual + half GEMM input)
    ln_k<<<M, 256>>>(src, g1, be1, xln, xln_h);
    // 2. QKV projection (fp32 out)
    hgemm_k<<<dim3(3 * d / 128, M / 128, 1), NTHREADS, SMEM_BYTES>>>(
        xln_h, d, 0, wqkv, d, 0, qkv, 3 * d, 0, d, bqkv, nullptr, 1.f, 0, 0, 0, 0);
    // 3. RoPE -> half Q,K
    rope_k<<<dim3(S, B), 256>>>(qkv, q_h, k_h);
    // 4. V transpose -> half
    vtrans_k<<<dim3(d / 32, S / 32, B), dim3(32, 8)>>>(qkv, vt_h);
    // 5. scores = scale * Q K^T (fp32 out, causal block skip)
    hgemm_k<<<dim3(S / 128, S / 128, B), NTHREADS, SMEM_BYTES>>>(
        q_h, d, Sd, k_h, d, Sd, sc, S, SS, d, nullptr, nullptr, attn_scale, 0, 1, 0, 0);
    // 6. softmax -> half probs
    softmax_k<<<dim3(S, B), 256>>>(sc, p_h);
    // 7. attn = P V (K truncated; half out)
    hgemm_k<<<dim3(d / 128, S / 128, B), NTHREADS, SMEM_BYTES>>>(
        p_h, S, SS, vt_h, S, Sd, at_h, d, Sd, S, nullptr, nullptr, 1.f, 0, 0, 1, 1);
    // 8. src2 = xln + attn Wo^T + bo (fp32 out)
    hgemm_k<<<dim3(d / 128, M / 128, 1), NTHREADS, SMEM_BYTES>>>(
        at_h, d, 0, wo, d, 0, src2, d, 0, d, bo, xln, 1.f, 0, 0, 0, 0);
    // 9. LN2 -> half
    ln_k<<<M, 256>>>(src2, g2, be2, hln, hln_h);
    // 10. h1 = relu(hln W1^T + b1) (half out)
    hgemm_k<<<dim3(f / 128, M / 128, 1), NTHREADS, SMEM_BYTES>>>(
        hln_h, d, 0, w1, d, 0, h1_h, f, 0, d, b1, nullptr, 1.f, 1, 0, 0, 1);
    // 11. out = src2 + h1 W2^T + b2 (fp32 out)
    hgemm_k<<<dim3(d / 128, M / 128, 1), NTHREADS, SMEM_BYTES>>>(
        h1_h, f, 0, w2, f, 0, out, d, 0, f, b2, src2, 1.f, 0, 0, 0, 0);
}

// round 8
// speedup vs baseline: 6.3346x; 1.0534x over previous
#include <cuda_runtime.h>
#include <cuda_fp16.h>
#include <math.h>
#include <stdint.h>

#define D_MODEL 2048
#define D_FF    8192
#define BATCH   4
#define SEQ     2048
#define NTOK    (BATCH * SEQ)

// ---------------------------------------------------------------------------
// Scratch
// ---------------------------------------------------------------------------
__device__ float  g_xln [(size_t)NTOK * D_MODEL];        // LN1 out fp32 (residual)
__device__ float  g_qkv [(size_t)NTOK * 3 * D_MODEL];    // QKV fp32
__device__ float  g_sc  [(size_t)BATCH * SEQ * SEQ];     // scores fp32
__device__ float  g_src2[(size_t)NTOK * D_MODEL];        // post-attn residual fp32
__device__ __half g_xln_h[(size_t)NTOK * D_MODEL];
__device__ __half g_q_h [(size_t)NTOK * D_MODEL];
__device__ __half g_k_h [(size_t)NTOK * D_MODEL];
__device__ __half g_vt_h[(size_t)NTOK * D_MODEL];        // V^T [B, d, S]
__device__ __half g_p_h [(size_t)BATCH * SEQ * SEQ];     // probs half
__device__ __half g_at_h[(size_t)NTOK * D_MODEL];        // attn half
__device__ __half g_hln_h[(size_t)NTOK * D_MODEL];
__device__ __half g_h1_h[(size_t)NTOK * D_FF];
__device__ __half g_wqkv[(size_t)3 * D_MODEL * D_MODEL];
__device__ __half g_wo  [(size_t)D_MODEL * D_MODEL];
__device__ __half g_w1  [(size_t)D_FF * D_MODEL];
__device__ __half g_w2  [(size_t)D_MODEL * D_FF];

__device__ __forceinline__ uint32_t smem_u32(const void* p) {
    uint32_t a;
    asm("{ .reg .u64 t; cvta.to.shared.u64 t, %1; cvt.u32.u64 %0, t; }" : "=r"(a) : "l"(p));
    return a;
}

#define MMA_F16(d, a, b)                                                       \
    asm volatile("mma.sync.aligned.m16n8k16.row.col.f32.f16.f16.f32 "          \
        "{%0,%1,%2,%3}, {%4,%5,%6,%7}, {%8,%9}, {%0,%1,%2,%3};"                \
        : "+f"((d)[0]), "+f"((d)[1]), "+f"((d)[2]), "+f"((d)[3])               \
        : "r"((a)[0]), "r"((a)[1]), "r"((a)[2]), "r"((a)[3]),                  \
          "r"((b)[0]), "r"((b)[1]))

#define LDM4(r0, r1, r2, r3, ad)                                               \
    asm volatile("ldmatrix.sync.aligned.m8n8.x4.shared.b16 {%0,%1,%2,%3}, [%4];" \
        : "=r"(r0), "=r"(r1), "=r"(r2), "=r"(r3) : "r"(ad))

#define CP16(dst, src) \
    asm volatile("cp.async.cg.shared.global [%0], [%1], 16;" :: "r"(dst), "l"(src))
#define CP_COMMIT() asm volatile("cp.async.commit_group;" ::: "memory")
#define CP_WAIT(n)  asm volatile("cp.async.wait_group %0;" :: "n"(n) : "memory")

// ---------------------------------------------------------------------------
// fp16 mma GEMM: C[M,N] = scale*(A @ B^T) [+bias][+res][relu]
// A:[M,K] half row-major, B:[N,K] half row-major. M,N mult 128, K mult 64.
// CTA 128x128x64, 4 warps (2x2), warp 64x64, m16n8k16, ldmatrix.x4 frags.
// 3-stage cp.async. Row pitch 72 halves (144 B): ldmatrix rows sweep all banks.
// ---------------------------------------------------------------------------
#define BK        64
#define PITCH_B   144                    // bytes per smem row
#define TILE_B    (128 * PITCH_B)        // 18432 B
#define STAGE_B   (2 * TILE_B)           // 36864 B
#define STAGES    3
#define SMEM_BYTES (STAGES * STAGE_B)    // 110592 B
#define NTHREADS  128

__global__ __launch_bounds__(NTHREADS)
void hgemm_k(const __half* __restrict__ A, int lda, long long sA,
             const __half* __restrict__ B, int ldb, long long sB,
             void*         __restrict__ Cv, int ldc, long long sC,
             int K,
             const float* __restrict__ bias,
             const float* __restrict__ res,
             float scale, int relu, int causal_skip, int klimit, int half_out)
{
    const int bm = blockIdx.y * 128;
    const int bn = blockIdx.x * 128;
    if (causal_skip && bn > bm) return;

    extern __shared__ float sm[];
    const uint32_t sbase = smem_u32(sm);

    const int tid = threadIdx.x;
    const int wid = tid >> 5;
    const int lane = tid & 31;
    const int g   = lane >> 2;
    const int tig = lane & 3;
    const int wm  = wid >> 1;
    const int wn  = wid & 1;
    // ldmatrix lane addressing: row within 16-row block, k-halfchunk select
    const uint32_t lrow = (lane & 7) + ((lane >> 3) & 1) * 8;
    const uint32_t lk16 = (lane >> 4) * 16;       // 0 or 16 bytes

    const long long bz = blockIdx.z;
    A += bz * sA;  B += bz * sB;
    const float* R = res ? res + bz * sC : nullptr;

    int Keff = K;
    if (klimit) { int kl = bm + 128; Keff = (kl < K) ? kl : K; }
    const int KT = Keff / BK;

    const __half* Abase = A + (long long)bm * lda;
    const __half* Bbase = B + (long long)bn * ldb;

#define ISSUE(kt_, st_) do {                                                   \
    const int _k0 = (kt_) * BK;                                                \
    const uint32_t _so = (uint32_t)(st_) * STAGE_B;                            \
    _Pragma("unroll")                                                          \
    for (int t = 0; t < 8; t++) {                                              \
        int c = tid + t * NTHREADS;                                            \
        int row = c >> 3, chk = c & 7;                                         \
        uint32_t w = (uint32_t)row * PITCH_B + (uint32_t)(chk << 4);           \
        CP16(sbase + _so + w,          Abase + (long long)row * lda + _k0 + (chk << 3)); \
        CP16(sbase + _so + TILE_B + w, Bbase + (long long)row * ldb + _k0 + (chk << 3)); \
    }                                                                          \
} while (0)

    float acc[4][8][4];
#pragma unroll
    for (int i = 0; i < 4; i++)
#pragma unroll
        for (int j = 0; j < 8; j++)
#pragma unroll
            for (int r = 0; r < 4; r++) acc[i][j][r] = 0.f;

#pragma unroll
    for (int s = 0; s < STAGES - 1; s++) { ISSUE(s, s); CP_COMMIT(); }
    CP_WAIT(STAGES - 2);
    __syncthreads();

    // per-thread smem base addrs for ldmatrix
    const uint32_t aAddr0 = sbase + (wm * 64 + lrow) * PITCH_B + lk16;
    const uint32_t bAddr0 = sbase + TILE_B + (wn * 64 + lrow) * PITCH_B + lk16;

    for (int kt = 0; kt < KT; kt++) {
        const int next = kt + STAGES - 1;
        if (next < KT) ISSUE(next, next % STAGES);
        CP_COMMIT();

        const uint32_t so = (uint32_t)(kt % STAGES) * STAGE_B;

#pragma unroll
        for (int ks = 0; ks < 4; ks++) {
            uint32_t a[4][4], b[8][2];
#pragma unroll
            for (int mf = 0; mf < 4; mf++)
                LDM4(a[mf][0], a[mf][1], a[mf][2], a[mf][3],
                     aAddr0 + so + (uint32_t)(mf * 16) * PITCH_B + ks * 32);
#pragma unroll
            for (int np = 0; np < 4; np++)
                LDM4(b[2 * np][0], b[2 * np + 1][0], b[2 * np][1], b[2 * np + 1][1],
                     bAddr0 + so + (uint32_t)(np * 16) * PITCH_B + ks * 32);
#pragma unroll
            for (int mf = 0; mf < 4; mf++)
#pragma unroll
                for (int nf = 0; nf < 8; nf++)
                    MMA_F16(acc[mf][nf], a[mf], b[nf]);
        }
        CP_WAIT(STAGES - 2);
        __syncthreads();
    }

    // epilogue: c0=(g,2tig) c1=(g,2tig+1) c2=(g+8,2tig) c3=(g+8,2tig+1)
    float*  Cf = (float*)Cv  + bz * sC;
    __half* Ch = (__half*)Cv + bz * sC;
#pragma unroll
    for (int mf = 0; mf < 4; mf++) {
        const int m0 = bm + wm * 64 + mf * 16 + g;
#pragma unroll
        for (int nf = 0; nf < 8; nf++) {
            const int n0 = bn + wn * 64 + nf * 8 + 2 * tig;
            float2 v0, v1;
            v0.x = acc[mf][nf][0] * scale; v0.y = acc[mf][nf][1] * scale;
            v1.x = acc[mf][nf][2] * scale; v1.y = acc[mf][nf][3] * scale;
            if (bias) {
                float bx = __ldg(bias + n0), by = __ldg(bias + n0 + 1);
                v0.x += bx; v0.y += by; v1.x += bx; v1.y += by;
            }
            if (R) {
                float2 r0 = *(const float2*)(R + (long long)m0 * ldc + n0);
                float2 r1 = *(const float2*)(R + (long long)(m0 + 8) * ldc + n0);
                v0.x += r0.x; v0.y += r0.y; v1.x += r1.x; v1.y += r1.y;
            }
            if (relu) {
                v0.x = fmaxf(v0.x, 0.f); v0.y = fmaxf(v0.y, 0.f);
                v1.x = fmaxf(v1.x, 0.f); v1.y = fmaxf(v1.y, 0.f);
            }
            if (half_out) {
                *(__half2*)(Ch + (long long)m0 * ldc + n0)       = __floats2half2_rn(v0.x, v0.y);
                *(__half2*)(Ch + (long long)(m0 + 8) * ldc + n0) = __floats2half2_rn(v1.x, v1.y);
            } else {
                *(float2*)(Cf + (long long)m0 * ldc + n0)       = v0;
                *(float2*)(Cf + (long long)(m0 + 8) * ldc + n0) = v1;
            }
        }
    }
}

// ---------------------------------------------------------------------------
// fp32 -> fp16 conversion (weights)
// ---------------------------------------------------------------------------
__global__ __launch_bounds__(256)
void cvt_k(const float* __restrict__ x, __half* __restrict__ y, long long n4)
{
    long long i = (long long)blockIdx.x * 256 + threadIdx.x;
    if (i < n4) {
        float4 v = ((const float4*)x)[i];
        __half2 h0 = __floats2half2_rn(v.x, v.y);
        __half2 h1 = __floats2half2_rn(v.z, v.w);
        ((uint2*)y)[i] = make_uint2(*(uint32_t*)&h0, *(uint32_t*)&h1);
    }
}

// ---------------------------------------------------------------------------
// LayerNorm: optional fp32 out (residual) + half out (GEMM input)
// ---------------------------------------------------------------------------
__global__ __launch_bounds__(256)
void ln_k(const float* __restrict__ x, const float* __restrict__ g,
          const float* __restrict__ b, float* __restrict__ y, __half* __restrict__ yh)
{
    const int D = D_MODEL;
    const long long row = blockIdx.x;
    const float* xr = x + row * D;
    __half*      hr = yh + row * D;
    const int tid = threadIdx.x;

    __shared__ float sh[256];
    float v[8];
    float s = 0.f;
#pragma unroll
    for (int i = 0; i < 8; i++) { v[i] = xr[tid + i * 256]; s += v[i]; }
    sh[tid] = s; __syncthreads();
    for (int o = 128; o > 0; o >>= 1) { if (tid < o) sh[tid] += sh[tid + o]; __syncthreads(); }
    const float mean = sh[0] * (1.f / D);
    __syncthreads();

    s = 0.f;
#pragma unroll
    for (int i = 0; i < 8; i++) { float d = v[i] - mean; s += d * d; }
    sh[tid] = s; __syncthreads();
    for (int o = 128; o > 0; o >>= 1) { if (tid < o) sh[tid] += sh[tid + o]; __syncthreads(); }
    const float r = rsqrtf(sh[0] * (1.f / D) + 1e-5f);

    float* yr = y ? y + row * D : nullptr;
#pragma unroll
    for (int i = 0; i < 8; i++) {
        int j = tid + i * 256;
        float o = (v[i] - mean) * r * __ldg(g + j) + __ldg(b + j);
        if (yr) yr[j] = o;
        hr[j] = __float2half_rn(o);
    }
}

// ---------------------------------------------------------------------------
// RoPE (reference-exact trig-of-trig), half outputs
// ---------------------------------------------------------------------------
__global__ __launch_bounds__(256)
void rope_k(const float* __restrict__ qkv, __half* __restrict__ Qo, __half* __restrict__ Ko)
{
    const int d = D_MODEL, half = D_MODEL / 2;
    const int t = blockIdx.x, b = blockIdx.y;
    const long long rq = ((long long)b * SEQ + t) * (3 * D_MODEL);
    const float* Q = qkv + rq;
    const float* K = qkv + rq + d;
    const long long ro = ((long long)b * SEQ + t) * d;
    const float pos = (float)t;

#pragma unroll
    for (int i = 0; i < 8; i++) {
        int j = threadIdx.x + i * 256;
        int fidx = (j < half) ? j : (j - half);
        float invf = powf(10000.0f, -(float)(2 * fidx) / (float)d);
        float sp = pos * invf;
        float e = (j < half) ? sinf(sp) : cosf(sp);
        float c = cosf(e), s = sinf(e);
        float rqv, rkv;
        if (j < half) { rqv = -Q[2 * j];              rkv = -K[2 * j]; }
        else          { rqv =  Q[2 * (j - half) + 1]; rkv =  K[2 * (j - half) + 1]; }
        Qo[ro + j] = __float2half_rn(Q[j] * c + rqv * s);
        Ko[ro + j] = __float2half_rn(K[j] * c - rkv * s);
    }
}

// ---------------------------------------------------------------------------
// V transpose -> half: vt[b, n, s] = qkv[b, s, 2d + n]
// ---------------------------------------------------------------------------
__global__ __launch_bounds__(256)
void vtrans_k(const float* __restrict__ qkv, __half* __restrict__ vt)
{
    __shared__ float t[32][33];
    const int b = blockIdx.z;
    const int s0 = blockIdx.y * 32, n0 = blockIdx.x * 32;
    const int x = threadIdx.x, y = threadIdx.y;
#pragma unroll
    for (int i = 0; i < 32; i += 8)
        t[y + i][x] = qkv[((long long)b * SEQ + s0 + y + i) * (3 * D_MODEL) + 2 * D_MODEL + n0 + x];
    __syncthreads();
#pragma unroll
    for (int i = 0; i < 32; i += 8)
        vt[((long long)b * D_MODEL + n0 + y + i) * SEQ + s0 + x] = __float2half_rn(t[x][y + i]);
}

// ---------------------------------------------------------------------------
// Causal softmax: fp32 scores in, half probs out (cols < ceil128(q+1))
// ---------------------------------------------------------------------------
__global__ __launch_bounds__(256)
void softmax_k(const float* __restrict__ S_, __half* __restrict__ P)
{
    const int S = SEQ;
    const int q = blockIdx.x, b = blockIdx.y;
    const float* row = S_ + ((long long)b * S + q) * S;
    __half* prow = P + ((long long)b * S + q) * S;
    const int n = q + 1;
    const int klim = ((q >> 7) + 1) << 7;
    const int tid = threadIdx.x;
    __shared__ float sh[256];

    float v[8];
    float mx = -3.402823e38f;
#pragma unroll
    for (int i = 0; i < 8; i++) {
        int j = tid + i * 256;
        v[i] = (j < n) ? row[j] : -3.402823e38f;
        mx = fmaxf(mx, v[i]);
    }
    sh[tid] = mx; __syncthreads();
    for (int o = 128; o > 0; o >>= 1) { if (tid < o) sh[tid] = fmaxf(sh[tid], sh[tid + o]); __syncthreads(); }
    mx = sh[0]; __syncthreads();

    float sum = 0.f;
#pragma unroll
    for (int i = 0; i < 8; i++) {
        int j = tid + i * 256;
        v[i] = (j < n) ? expf(v[i] - mx) : 0.f;
        sum += v[i];
    }
    sh[tid] = sum; __syncthreads();
    for (int o = 128; o > 0; o >>= 1) { if (tid < o) sh[tid] += sh[tid + o]; __syncthreads(); }
    const float inv = 1.f / sh[0];

#pragma unroll
    for (int i = 0; i < 8; i++) {
        int j = tid + i * 256;
        if (j < klim) prow[j] = __float2half_rn(v[i] * inv);
    }
}

// ---------------------------------------------------------------------------
// Launch
// ---------------------------------------------------------------------------
extern "C" void kernel_launch(void* const* d_in, const int* in_sizes, int n_in,
                              void* d_out, int out_size)
{
    const float* src  = (const float*)d_in[0];
    const float* Wqkv = (const float*)d_in[1];
    const float* bqkv = (const float*)d_in[2];
    const float* Wo   = (const float*)d_in[3];
    const float* bo   = (const float*)d_in[4];
    const float* W1   = (const float*)d_in[5];
    const float* b1   = (const float*)d_in[6];
    const float* W2   = (const float*)d_in[7];
    const float* b2   = (const float*)d_in[8];
    const float* g1   = (const float*)d_in[9];
    const float* be1  = (const float*)d_in[10];
    const float* g2   = (const float*)d_in[11];
    const float* be2  = (const float*)d_in[12];
    float* out = (float*)d_out;

    float *xln, *qkv, *sc, *src2;
    __half *xln_h, *q_h, *k_h, *vt_h, *p_h, *at_h, *hln_h, *h1_h;
    __half *wqkv, *wo, *w1, *w2;
    cudaGetSymbolAddress((void**)&xln,   g_xln);
    cudaGetSymbolAddress((void**)&qkv,   g_qkv);
    cudaGetSymbolAddress((void**)&sc,    g_sc);
    cudaGetSymbolAddress((void**)&src2,  g_src2);
    cudaGetSymbolAddress((void**)&xln_h, g_xln_h);
    cudaGetSymbolAddress((void**)&q_h,   g_q_h);
    cudaGetSymbolAddress((void**)&k_h,   g_k_h);
    cudaGetSymbolAddress((void**)&vt_h,  g_vt_h);
    cudaGetSymbolAddress((void**)&p_h,   g_p_h);
    cudaGetSymbolAddress((void**)&at_h,  g_at_h);
    cudaGetSymbolAddress((void**)&hln_h, g_hln_h);
    cudaGetSymbolAddress((void**)&h1_h,  g_h1_h);
    cudaGetSymbolAddress((void**)&wqkv,  g_wqkv);
    cudaGetSymbolAddress((void**)&wo,    g_wo);
    cudaGetSymbolAddress((void**)&w1,    g_w1);
    cudaGetSymbolAddress((void**)&w2,    g_w2);

    cudaFuncSetAttribute(hgemm_k, cudaFuncAttributeMaxDynamicSharedMemorySize, SMEM_BYTES);

    const int d = D_MODEL, f = D_FF, S = SEQ, B = BATCH, M = NTOK;
    const long long Sd = (long long)S * d;
    const long long SS = (long long)S * S;
    const float attn_scale = 1.0f / sqrtf((float)d);

    // 0. convert weights to fp16
    {
        long long n4;
        n4 = (long long)3 * d * d / 4; cvt_k<<<(unsigned)((n4 + 255) / 256), 256>>>(Wqkv, wqkv, n4);
        n4 = (long long)d * d / 4;     cvt_k<<<(unsigned)((n4 + 255) / 256), 256>>>(Wo,   wo,   n4);
        n4 = (long long)f * d / 4;     cvt_k<<<(unsigned)((n4 + 255) / 256), 256>>>(W1,   w1,   n4);
        n4 = (long long)d * f / 4;     cvt_k<<<(unsigned)((n4 + 255) / 256), 256>>>(W2,   w2,   n4);
    }
    // 1. LN1 (fp32 residual + half GEMM input)
    ln_k<<<M, 256>>>(src, g1, be1, xln, xln_h);
    // 2. QKV projection (fp32 out)
    hgemm_k<<<dim3(3 * d / 128, M / 128, 1), NTHREADS, SMEM_BYTES>>>(
        xln_h, d, 0, wqkv, d, 0, qkv, 3 * d, 0, d, bqkv, nullptr, 1.f, 0, 0, 0, 0);
    // 3. RoPE -> half Q,K
    rope_k<<<dim3(S, B), 256>>>(qkv, q_h, k_h);
    // 4. V transpose -> half
    vtrans_k<<<dim3(d / 32, S / 32, B), dim3(32, 8)>>>(qkv, vt_h);
    // 5. scores = scale * Q K^T (fp32 out, causal block skip)
    hgemm_k<<<dim3(S / 128, S / 128, B), NTHREADS, SMEM_BYTES>>>(
        q_h, d, Sd, k_h, d, Sd, sc, S, SS, d, nullptr, nullptr, attn_scale, 0, 1, 0, 0);
    // 6. softmax -> half probs
    softmax_k<<<dim3(S, B), 256>>>(sc, p_h);
    // 7. attn = P V (K truncated; half out)
    hgemm_k<<<dim3(d / 128, S / 128, B), NTHREADS, SMEM_BYTES>>>(
        p_h, S, SS, vt_h, S, Sd, at_h, d, Sd, S, nullptr, nullptr, 1.f, 0, 0, 1, 1);
    // 8. src2 = xln + attn Wo^T + bo (fp32 out)
    hgemm_k<<<dim3(d / 128, M / 128, 1), NTHREADS, SMEM_BYTES>>>(
        at_h, d, 0, wo, d, 0, src2, d, 0, d, bo, xln, 1.f, 0, 0, 0, 0);
    // 9. LN2 -> half only
    ln_k<<<M, 256>>>(src2, g2, be2, nullptr, hln_h);
    // 10. h1 = relu(hln W1^T + b1) (half out)
    hgemm_k<<<dim3(f / 128, M / 128, 1), NTHREADS, SMEM_BYTES>>>(
        hln_h, d, 0, w1, d, 0, h1_h, f, 0, d, b1, nullptr, 1.f, 1, 0, 0, 1);
    // 11. out = src2 + h1 W2^T + b2 (fp32 out)
    hgemm_k<<<dim3(d / 128, M / 128, 1), NTHREADS, SMEM_BYTES>>>(
        h1_h, f, 0, w2, f, 0, out, d, 0, f, b2, src2, 1.f, 0, 0, 0, 0);
}